// round 1
// baseline (speedup 1.0000x reference)
#include <cuda_runtime.h>
#include <cuda_bf16.h>
#include <mma.h>

using namespace nvcuda;

// Problem dims
#define DIM_B    16
#define DIM_K    8
#define DIM_N    196
#define DIM_D    768
#define DIM_H    3072
#define DIM_DOUT 768

#define M2 (DIM_B * DIM_N)   // 3136 reduced rows (b*196+n)

// Scratch: G[bn][h] = (1/8) * sum_k relu((slots[b,k]+pos[n]) @ W1 + b1)
__device__ float g_G[M2 * DIM_H];

// ---------------------------------------------------------------------------
// Pass 1: fused  A(25088x768, rows ordered (b,n,k)) @ W1(768x3072)
//         epilogue: +b1, relu, reduce groups of 8 rows (k), *1/8 -> g_G
// BM=128 BN=128 BK=32, 256 threads, wmma m16n16k8 tf32
// ---------------------------------------------------------------------------
__global__ __launch_bounds__(256, 2) void pass1_kernel(
    const float* __restrict__ slots,   // [B*K, D]
    const float* __restrict__ pos,     // [N, D]
    const float* __restrict__ W1,      // [D, H]
    const float* __restrict__ b1)      // [H]
{
    constexpr int BM = 128, BN = 128, BK = 32;
    constexpr int LDA = 36;    // padded
    constexpr int LDB = 136;   // padded
    constexpr int LDC = 132;   // padded

    __shared__ union {
        struct {
            float A[BM * LDA];   // 128x36
            float B[BK * LDB];   // 32x136
        } t;
        float C[64 * LDC];       // epilogue buffer (half of C tile)
    } sm;

    const int h0  = blockIdx.x * BN;   // 0..23 tiles of H
    const int m0  = blockIdx.y * BM;   // 0..195 tiles of M
    const int tid = threadIdx.x;
    const int wid = tid >> 5;
    const int warp_m = wid >> 1;       // 0..3 -> 32 rows each
    const int warp_n = wid & 1;        // 0..1 -> 64 cols each

    wmma::fragment<wmma::accumulator, 16, 16, 8, float> acc[2][4];
#pragma unroll
    for (int i = 0; i < 2; i++)
#pragma unroll
        for (int j = 0; j < 4; j++)
            wmma::fill_fragment(acc[i][j], 0.0f);

    for (int k0 = 0; k0 < DIM_D; k0 += BK) {
        // ---- load A tile 128x32 (computed on the fly: slots + pos) ----
#pragma unroll
        for (int i = 0; i < 16; i++) {
            int e = i * 256 + tid;
            int r = e >> 5;          // 0..127
            int c = e & 31;          // 0..31
            int m  = m0 + r;         // global row, ordered (b, n, k)
            int kk = m & 7;
            int bn = m >> 3;
            int b  = bn / DIM_N;
            int n  = bn - b * DIM_N;
            float v = slots[(b * DIM_K + kk) * DIM_D + k0 + c]
                    + pos[n * DIM_D + k0 + c];
            sm.t.A[r * LDA + c] = wmma::__float_to_tf32(v);
        }
        // ---- load B tile 32x128 from W1 (row-major k x n) ----
#pragma unroll
        for (int i = 0; i < 16; i++) {
            int e = i * 256 + tid;
            int r = e >> 7;          // 0..31
            int c = e & 127;         // 0..127
            sm.t.B[r * LDB + c] =
                wmma::__float_to_tf32(W1[(k0 + r) * DIM_H + h0 + c]);
        }
        __syncthreads();

#pragma unroll
        for (int ks = 0; ks < BK; ks += 8) {
            wmma::fragment<wmma::matrix_a, 16, 16, 8, wmma::precision::tf32,
                           wmma::row_major> af[2];
            wmma::fragment<wmma::matrix_b, 16, 16, 8, wmma::precision::tf32,
                           wmma::row_major> bf[4];
#pragma unroll
            for (int i = 0; i < 2; i++)
                wmma::load_matrix_sync(
                    af[i], &sm.t.A[(warp_m * 32 + i * 16) * LDA + ks], LDA);
#pragma unroll
            for (int j = 0; j < 4; j++)
                wmma::load_matrix_sync(
                    bf[j], &sm.t.B[ks * LDB + warp_n * 64 + j * 16], LDB);
#pragma unroll
            for (int i = 0; i < 2; i++)
#pragma unroll
                for (int j = 0; j < 4; j++)
                    wmma::mma_sync(acc[i][j], af[i], bf[j], acc[i][j]);
        }
        __syncthreads();
    }

    // ---- epilogue: 2 phases of 64 rows; +bias, relu, reduce k-groups ----
#pragma unroll
    for (int ph = 0; ph < 2; ph++) {
        if ((warp_m >> 1) == ph) {
            int rbase = (warp_m & 1) * 32;
#pragma unroll
            for (int i = 0; i < 2; i++)
#pragma unroll
                for (int j = 0; j < 4; j++)
                    wmma::store_matrix_sync(
                        &sm.C[(rbase + i * 16) * LDC + warp_n * 64 + j * 16],
                        acc[i][j], LDC, wmma::mem_row_major);
        }
        __syncthreads();
        // reduce 8 groups x 128 cols -> 1024 outputs
        for (int o = tid; o < 1024; o += 256) {
            int g = o >> 7;      // group 0..7
            int c = o & 127;     // col
            float bias = b1[h0 + c];
            float s = 0.0f;
#pragma unroll
            for (int kk = 0; kk < 8; kk++) {
                float v = sm.C[(g * 8 + kk) * LDC + c] + bias;
                s += fmaxf(v, 0.0f);
            }
            int grow = (m0 >> 3) + ph * 8 + g;   // bn index
            g_G[grow * DIM_H + h0 + c] = s * 0.125f;
        }
        __syncthreads();
    }
}

// ---------------------------------------------------------------------------
// Pass 2: out(3136x768) = G(3136x3072) @ W2(3072x768) + b2
// BM=64 BN=128 BK=32, 256 threads (warp grid 2x4, warp tile 32x32)
// 3136 = 64*49 exactly, 768 = 128*6 exactly -> no bounds checks
// ---------------------------------------------------------------------------
__global__ __launch_bounds__(256, 2) void pass2_kernel(
    const float* __restrict__ W2,   // [H, DOUT]
    const float* __restrict__ b2,   // [DOUT]
    float* __restrict__ out)        // [M2, DOUT]
{
    constexpr int BM = 64, BN = 128, BK = 32;
    constexpr int LDA = 36;
    constexpr int LDB = 136;
    constexpr int LDC = 132;

    __shared__ union {
        struct {
            float A[BM * LDA];   // 64x36
            float B[BK * LDB];   // 32x136
        } t;
        float C[BM * LDC];       // 64x132
    } sm;

    const int o0  = blockIdx.x * BN;
    const int m0  = blockIdx.y * BM;
    const int tid = threadIdx.x;
    const int wid = tid >> 5;
    const int warp_m = wid >> 2;   // 0..1 -> 32 rows
    const int warp_n = wid & 3;    // 0..3 -> 32 cols

    wmma::fragment<wmma::accumulator, 16, 16, 8, float> acc[2][2];
#pragma unroll
    for (int i = 0; i < 2; i++)
#pragma unroll
        for (int j = 0; j < 2; j++)
            wmma::fill_fragment(acc[i][j], 0.0f);

    for (int k0 = 0; k0 < DIM_H; k0 += BK) {
        // A tile 64x32 from g_G
#pragma unroll
        for (int i = 0; i < 8; i++) {
            int e = i * 256 + tid;
            int r = e >> 5;
            int c = e & 31;
            sm.t.A[r * LDA + c] =
                wmma::__float_to_tf32(g_G[(m0 + r) * DIM_H + k0 + c]);
        }
        // B tile 32x128 from W2
#pragma unroll
        for (int i = 0; i < 16; i++) {
            int e = i * 256 + tid;
            int r = e >> 7;
            int c = e & 127;
            sm.t.B[r * LDB + c] =
                wmma::__float_to_tf32(W2[(k0 + r) * DIM_DOUT + o0 + c]);
        }
        __syncthreads();

#pragma unroll
        for (int ks = 0; ks < BK; ks += 8) {
            wmma::fragment<wmma::matrix_a, 16, 16, 8, wmma::precision::tf32,
                           wmma::row_major> af[2];
            wmma::fragment<wmma::matrix_b, 16, 16, 8, wmma::precision::tf32,
                           wmma::row_major> bf[2];
#pragma unroll
            for (int i = 0; i < 2; i++)
                wmma::load_matrix_sync(
                    af[i], &sm.t.A[(warp_m * 32 + i * 16) * LDA + ks], LDA);
#pragma unroll
            for (int j = 0; j < 2; j++)
                wmma::load_matrix_sync(
                    bf[j], &sm.t.B[ks * LDB + warp_n * 32 + j * 16], LDB);
#pragma unroll
            for (int i = 0; i < 2; i++)
#pragma unroll
                for (int j = 0; j < 2; j++)
                    wmma::mma_sync(acc[i][j], af[i], bf[j], acc[i][j]);
        }
        __syncthreads();
    }

    // epilogue: store to smem, add bias, write out
#pragma unroll
    for (int i = 0; i < 2; i++)
#pragma unroll
        for (int j = 0; j < 2; j++)
            wmma::store_matrix_sync(
                &sm.C[(warp_m * 32 + i * 16) * LDC + warp_n * 32 + j * 16],
                acc[i][j], LDC, wmma::mem_row_major);
    __syncthreads();

    for (int o = tid; o < BM * BN; o += 256) {
        int r = o >> 7;
        int c = o & 127;
        out[(m0 + r) * DIM_DOUT + o0 + c] = sm.C[r * LDC + c] + b2[o0 + c];
    }
}

// ---------------------------------------------------------------------------
extern "C" void kernel_launch(void* const* d_in, const int* in_sizes, int n_in,
                              void* d_out, int out_size)
{
    const float* slots = (const float*)d_in[0];   // (16,8,768)
    const float* pos   = (const float*)d_in[1];   // (196,768)
    // d_in[2] = map_alpha : softmax over K of identical values == 1/8 exactly
    const float* W1    = (const float*)d_in[3];   // (768,3072)
    const float* b1    = (const float*)d_in[4];   // (3072,)
    const float* W2    = (const float*)d_in[5];   // (3072,768)
    const float* b2    = (const float*)d_in[6];   // (768,)
    float* out = (float*)d_out;                   // (16,196,768)

    dim3 g1(DIM_H / 128, (DIM_B * DIM_N * DIM_K) / 128);   // (24, 196)
    pass1_kernel<<<g1, 256>>>(slots, pos, W1, b1);

    dim3 g2(DIM_DOUT / 128, M2 / 64);                      // (6, 49)
    pass2_kernel<<<g2, 256>>>(W2, b2, out);
}

// round 3
// speedup vs baseline: 5.9788x; 5.9788x over previous
#include <cuda_runtime.h>
#include <cuda_bf16.h>
#include <mma.h>
#include <cstdint>

using namespace nvcuda;

// Problem dims
#define DIM_B    16
#define DIM_K    8
#define DIM_N    196
#define DIM_D    768
#define DIM_H    3072
#define DIM_DOUT 768

#define M2 (DIM_B * DIM_N)   // 3136 reduced rows (b*196+n)
#define MSP 324              // 128 slot rows + 196 pos rows
#define MSP_PAD 384          // padded to 64-multiple

// Scratch
__device__ float g_SP1[MSP_PAD * DIM_H];   // rows 0..127: slots@W1, 128..323: pos@W1
__device__ float g_G[M2 * DIM_H];          // tf32-converted combined hidden (pre-GEMM2 A)
__device__ float g_W2c[DIM_H * DIM_DOUT];  // tf32-converted W2

// ---------------------------------------------------------------------------
// cp.async helpers
// ---------------------------------------------------------------------------
__device__ __forceinline__ void cp16(void* smem_dst, const void* gmem_src) {
    unsigned int d = (unsigned int)__cvta_generic_to_shared(smem_dst);
    asm volatile("cp.async.cg.shared.global [%0], [%1], 16;\n" :: "r"(d), "l"(gmem_src));
}
__device__ __forceinline__ void cp_commit() {
    asm volatile("cp.async.commit_group;\n");
}
__device__ __forceinline__ void cp_wait0() {
    asm volatile("cp.async.wait_group 0;\n");
}

// ---------------------------------------------------------------------------
// Kernel 0: convert W2 to tf32 (round-to-nearest) once, so pass2 cp.asyncs raw
// ---------------------------------------------------------------------------
__global__ void convw2_kernel(const float* __restrict__ W2) {
    int i = (blockIdx.x * 256 + threadIdx.x) * 4;
    float4 v = *(const float4*)&W2[i];
    v.x = wmma::__float_to_tf32(v.x);
    v.y = wmma::__float_to_tf32(v.y);
    v.z = wmma::__float_to_tf32(v.z);
    v.w = wmma::__float_to_tf32(v.w);
    *(float4*)&g_W2c[i] = v;
}

// ---------------------------------------------------------------------------
// Kernel 1: tiny GEMM  [slots; pos] (324x768) @ W1 (768x3072) -> g_SP1
// BM=64 BN=128 BK=32, 256 threads, direct wmma store to global
// ---------------------------------------------------------------------------
__global__ __launch_bounds__(256, 2) void gemm_small_kernel(
    const float* __restrict__ slots,
    const float* __restrict__ pos,
    const float* __restrict__ W1)
{
    constexpr int BM = 64, BN = 128, BK = 32;
    constexpr int LDA = 36, LDB = 136;

    __shared__ float sA[BM * LDA];
    __shared__ float sB[BK * LDB];

    const int h0  = blockIdx.x * BN;
    const int m0  = blockIdx.y * BM;
    const int tid = threadIdx.x;
    const int wid = tid >> 5;
    const int warp_m = wid >> 2;   // 0..1
    const int warp_n = wid & 3;    // 0..3

    wmma::fragment<wmma::accumulator, 16, 16, 8, float> acc[2][2];
#pragma unroll
    for (int i = 0; i < 2; i++)
#pragma unroll
        for (int j = 0; j < 2; j++)
            wmma::fill_fragment(acc[i][j], 0.0f);

    for (int k0 = 0; k0 < DIM_D; k0 += BK) {
#pragma unroll
        for (int i = 0; i < 8; i++) {
            int e = i * 256 + tid;
            int r = e >> 5, c = e & 31;
            int m = m0 + r;
            float v = 0.0f;
            if (m < 128)      v = slots[m * DIM_D + k0 + c];
            else if (m < MSP) v = pos[(m - 128) * DIM_D + k0 + c];
            sA[r * LDA + c] = wmma::__float_to_tf32(v);
        }
#pragma unroll
        for (int i = 0; i < 16; i++) {
            int e = i * 256 + tid;
            int r = e >> 7, c = e & 127;
            sB[r * LDB + c] = wmma::__float_to_tf32(W1[(k0 + r) * DIM_H + h0 + c]);
        }
        __syncthreads();

#pragma unroll
        for (int ks = 0; ks < BK; ks += 8) {
            wmma::fragment<wmma::matrix_a, 16, 16, 8, wmma::precision::tf32,
                           wmma::row_major> af[2];
            wmma::fragment<wmma::matrix_b, 16, 16, 8, wmma::precision::tf32,
                           wmma::row_major> bf[2];
#pragma unroll
            for (int i = 0; i < 2; i++)
                wmma::load_matrix_sync(af[i], &sA[(warp_m * 32 + i * 16) * LDA + ks], LDA);
#pragma unroll
            for (int j = 0; j < 2; j++)
                wmma::load_matrix_sync(bf[j], &sB[ks * LDB + warp_n * 32 + j * 16], LDB);
#pragma unroll
            for (int i = 0; i < 2; i++)
#pragma unroll
                for (int j = 0; j < 2; j++)
                    wmma::mma_sync(acc[i][j], af[i], bf[j], acc[i][j]);
        }
        __syncthreads();
    }

    // direct store to g_SP1 (padded to 384 rows, OOB rows are scratch)
#pragma unroll
    for (int i = 0; i < 2; i++)
#pragma unroll
        for (int j = 0; j < 2; j++)
            wmma::store_matrix_sync(
                &g_SP1[(m0 + warp_m * 32 + i * 16) * DIM_H + h0 + warp_n * 32 + j * 16],
                acc[i][j], DIM_H, wmma::mem_row_major);
}

// ---------------------------------------------------------------------------
// Kernel 2: combine  G[b*196+n, h] = tf32( 0.125 * sum_k relu(S1[b,k,h] + P1[n,h] + b1[h]) )
// grid (4 n-chunks, 3 h-chunks, 16 b), 256 threads, each thread owns 4 h cols
// S1 values for fixed (b, h-slice) live in registers across all n.
// ---------------------------------------------------------------------------
__global__ __launch_bounds__(256) void combine_kernel(const float* __restrict__ b1)
{
    const int b  = blockIdx.z;
    const int h0 = blockIdx.y * 1024 + threadIdx.x * 4;
    const int n0 = blockIdx.x * 49;

    float4 s[8];
#pragma unroll
    for (int k = 0; k < 8; k++)
        s[k] = *(const float4*)&g_SP1[(b * 8 + k) * DIM_H + h0];
    float4 bb = *(const float4*)&b1[h0];
#pragma unroll
    for (int k = 0; k < 8; k++) {
        s[k].x += bb.x; s[k].y += bb.y; s[k].z += bb.z; s[k].w += bb.w;
    }

    for (int n = 0; n < 49; n++) {
        int nn = n0 + n;
        float4 p = *(const float4*)&g_SP1[(128 + nn) * DIM_H + h0];
        float4 a;
        a.x = a.y = a.z = a.w = 0.0f;
#pragma unroll
        for (int k = 0; k < 8; k++) {
            a.x += fmaxf(s[k].x + p.x, 0.0f);
            a.y += fmaxf(s[k].y + p.y, 0.0f);
            a.z += fmaxf(s[k].z + p.z, 0.0f);
            a.w += fmaxf(s[k].w + p.w, 0.0f);
        }
        a.x = wmma::__float_to_tf32(a.x * 0.125f);
        a.y = wmma::__float_to_tf32(a.y * 0.125f);
        a.z = wmma::__float_to_tf32(a.z * 0.125f);
        a.w = wmma::__float_to_tf32(a.w * 0.125f);
        *(float4*)&g_G[(b * DIM_N + nn) * DIM_H + h0] = a;
    }
}

// ---------------------------------------------------------------------------
// Pass 2: out(3136x768) = G(3136x3072) @ W2c(3072x768) + b2
// BM=64 BN=128 BK=32, 256 threads, cp.async double-buffered (dynamic smem)
// ---------------------------------------------------------------------------
__global__ __launch_bounds__(256, 2) void pass2_kernel(
    const float* __restrict__ b2,
    float* __restrict__ out)
{
    constexpr int BM = 64, BN = 128, BK = 32;
    constexpr int LDA = 36, LDB = 136, LDC = 132;
    constexpr int ASZ = BM * LDA;   // 2304 floats
    constexpr int BSZ = BK * LDB;   // 4352 floats
    constexpr int KT  = DIM_H / BK; // 96

    extern __shared__ float smx[];
    float* As = smx;               // 2 * ASZ
    float* Bs = smx + 2 * ASZ;     // 2 * BSZ
    float* Cs = smx;               // epilogue reuse (64*132 <= total)

    const int o0  = blockIdx.x * BN;
    const int m0  = blockIdx.y * BM;
    const int tid = threadIdx.x;
    const int wid = tid >> 5;
    const int warp_m = wid >> 2;   // 0..1
    const int warp_n = wid & 3;    // 0..3

    wmma::fragment<wmma::accumulator, 16, 16, 8, float> acc[2][2];
#pragma unroll
    for (int i = 0; i < 2; i++)
#pragma unroll
        for (int j = 0; j < 2; j++)
            wmma::fill_fragment(acc[i][j], 0.0f);

    // A-tile: 64x32 = 512 float4, 2 per thread. B-tile: 32x128 = 1024 float4, 4/thread.
    const int ar0 = tid >> 3, ac4 = (tid & 7) * 4;         // +32 rows on 2nd
    const int br0 = tid >> 5, bc4 = (tid & 31) * 4;        // +8 rows x4

#define LOAD_TILES(kt, buf)                                                      \
    {                                                                            \
        const float* gA = g_G + (size_t)m0 * DIM_H + (kt) * BK;                  \
        float* sA = As + (buf) * ASZ;                                            \
        cp16(sA + ar0 * LDA + ac4,        gA + (size_t)ar0 * DIM_H + ac4);       \
        cp16(sA + (ar0 + 32) * LDA + ac4, gA + (size_t)(ar0 + 32) * DIM_H + ac4);\
        const float* gB = g_W2c + (size_t)(kt) * BK * DIM_DOUT + o0;             \
        float* sB = Bs + (buf) * BSZ;                                            \
        cp16(sB + br0 * LDB + bc4,        gB + (size_t)br0 * DIM_DOUT + bc4);    \
        cp16(sB + (br0 + 8) * LDB + bc4,  gB + (size_t)(br0 + 8) * DIM_DOUT + bc4); \
        cp16(sB + (br0 + 16) * LDB + bc4, gB + (size_t)(br0 + 16) * DIM_DOUT + bc4);\
        cp16(sB + (br0 + 24) * LDB + bc4, gB + (size_t)(br0 + 24) * DIM_DOUT + bc4);\
    }

    LOAD_TILES(0, 0);
    cp_commit();

    int buf = 0;
    for (int kt = 0; kt < KT; kt++) {
        cp_wait0();
        __syncthreads();
        if (kt + 1 < KT) {
            LOAD_TILES(kt + 1, buf ^ 1);
            cp_commit();
        }
        float* sA = As + buf * ASZ;
        float* sB = Bs + buf * BSZ;
#pragma unroll
        for (int ks = 0; ks < BK; ks += 8) {
            wmma::fragment<wmma::matrix_a, 16, 16, 8, wmma::precision::tf32,
                           wmma::row_major> af[2];
            wmma::fragment<wmma::matrix_b, 16, 16, 8, wmma::precision::tf32,
                           wmma::row_major> bf[2];
#pragma unroll
            for (int i = 0; i < 2; i++)
                wmma::load_matrix_sync(af[i], &sA[(warp_m * 32 + i * 16) * LDA + ks], LDA);
#pragma unroll
            for (int j = 0; j < 2; j++)
                wmma::load_matrix_sync(bf[j], &sB[ks * LDB + warp_n * 32 + j * 16], LDB);
#pragma unroll
            for (int i = 0; i < 2; i++)
#pragma unroll
                for (int j = 0; j < 2; j++)
                    wmma::mma_sync(acc[i][j], af[i], bf[j], acc[i][j]);
        }
        __syncthreads();
        buf ^= 1;
    }
#undef LOAD_TILES

    // epilogue via smem (reuses tile space), add bias, write out
#pragma unroll
    for (int i = 0; i < 2; i++)
#pragma unroll
        for (int j = 0; j < 2; j++)
            wmma::store_matrix_sync(
                &Cs[(warp_m * 32 + i * 16) * LDC + warp_n * 32 + j * 16],
                acc[i][j], LDC, wmma::mem_row_major);
    __syncthreads();

    for (int o = tid; o < BM * BN; o += 256) {
        int r = o >> 7, c = o & 127;
        out[(size_t)(m0 + r) * DIM_DOUT + o0 + c] = Cs[r * LDC + c] + b2[o0 + c];
    }
}

// ---------------------------------------------------------------------------
extern "C" void kernel_launch(void* const* d_in, const int* in_sizes, int n_in,
                              void* d_out, int out_size)
{
    const float* slots = (const float*)d_in[0];   // (16,8,768)
    const float* pos   = (const float*)d_in[1];   // (196,768)
    // d_in[2] = map_alpha : softmax over K of identical values == 1/8 exactly
    const float* W1    = (const float*)d_in[3];   // (768,3072)
    const float* b1    = (const float*)d_in[4];   // (3072,)
    const float* W2    = (const float*)d_in[5];   // (3072,768)
    const float* b2    = (const float*)d_in[6];   // (768,)
    float* out = (float*)d_out;                   // (16,196,768)

    // pass2 dynamic smem: 2*(2304+4352)*4 = 53248 bytes (> 48KB default)
    static_assert(2 * (64 * 36 + 32 * 136) * 4 == 53248, "smem size");
    cudaFuncSetAttribute(pass2_kernel,
                         cudaFuncAttributeMaxDynamicSharedMemorySize, 53248);

    convw2_kernel<<<(DIM_H * DIM_DOUT) / 1024, 256>>>(W2);

    dim3 gs(DIM_H / 128, MSP_PAD / 64);             // (24, 6)
    gemm_small_kernel<<<gs, 256>>>(slots, pos, W1);

    dim3 gc(4, 3, DIM_B);                           // n-chunks, h-chunks, b
    combine_kernel<<<gc, 256>>>(b1);

    dim3 g2(DIM_DOUT / 128, M2 / 64);               // (6, 49)
    pass2_kernel<<<g2, 256, 53248>>>(b2, out);
}

// round 5
// speedup vs baseline: 6.1782x; 1.0333x over previous
#include <cuda_runtime.h>
#include <cuda_bf16.h>
#include <mma.h>
#include <cstdint>

using namespace nvcuda;

// Problem dims
#define DIM_B    16
#define DIM_K    8
#define DIM_N    196
#define DIM_D    768
#define DIM_H    3072
#define DIM_DOUT 768

#define M2      (DIM_B * DIM_N)   // 3136 reduced rows (b*196+n)
#define M2_PAD  3200              // padded to 128-multiple (25*128)
#define MSP     324               // 128 slot rows + 196 pos rows
#define MSP_PAD 384               // padded to 64-multiple

// Scratch (zero-initialized at module load; padded G rows stay 0 forever)
__device__ float g_SP1[MSP_PAD * DIM_H];   // rows 0..127: slots@W1, 128..323: pos@W1
__device__ float g_G[M2_PAD * DIM_H];      // combined hidden (GEMM2 A operand)
__device__ float g_W2c[DIM_H * DIM_DOUT];  // tf32-converted (RN) W2

// ---------------------------------------------------------------------------
// cp.async helpers
// ---------------------------------------------------------------------------
__device__ __forceinline__ void cp16(void* smem_dst, const void* gmem_src) {
    unsigned int d = (unsigned int)__cvta_generic_to_shared(smem_dst);
    asm volatile("cp.async.cg.shared.global [%0], [%1], 16;\n" :: "r"(d), "l"(gmem_src));
}
__device__ __forceinline__ void cp_commit() {
    asm volatile("cp.async.commit_group;\n");
}
__device__ __forceinline__ void cp_wait0() {
    asm volatile("cp.async.wait_group 0;\n");
}

// ---------------------------------------------------------------------------
// Kernel 0: convert W2 to tf32 (round-to-nearest) once
// ---------------------------------------------------------------------------
__global__ void convw2_kernel(const float* __restrict__ W2) {
    int i = (blockIdx.x * 256 + threadIdx.x) * 4;
    float4 v = *(const float4*)&W2[i];
    v.x = wmma::__float_to_tf32(v.x);
    v.y = wmma::__float_to_tf32(v.y);
    v.z = wmma::__float_to_tf32(v.z);
    v.w = wmma::__float_to_tf32(v.w);
    *(float4*)&g_W2c[i] = v;
}

// ---------------------------------------------------------------------------
// Kernel 1: tiny GEMM  [slots; pos] (324x768) @ W1 (768x3072) -> g_SP1
// ---------------------------------------------------------------------------
__global__ __launch_bounds__(256, 2) void gemm_small_kernel(
    const float* __restrict__ slots,
    const float* __restrict__ pos,
    const float* __restrict__ W1)
{
    constexpr int BM = 64, BN = 128, BK = 32;
    constexpr int LDA = 36, LDB = 136;

    __shared__ float sA[BM * LDA];
    __shared__ float sB[BK * LDB];

    const int h0  = blockIdx.x * BN;
    const int m0  = blockIdx.y * BM;
    const int tid = threadIdx.x;
    const int wid = tid >> 5;
    const int warp_m = wid >> 2;   // 0..1
    const int warp_n = wid & 3;    // 0..3

    wmma::fragment<wmma::accumulator, 16, 16, 8, float> acc[2][2];
#pragma unroll
    for (int i = 0; i < 2; i++)
#pragma unroll
        for (int j = 0; j < 2; j++)
            wmma::fill_fragment(acc[i][j], 0.0f);

    for (int k0 = 0; k0 < DIM_D; k0 += BK) {
#pragma unroll
        for (int i = 0; i < 8; i++) {
            int e = i * 256 + tid;
            int r = e >> 5, c = e & 31;
            int m = m0 + r;
            float v = 0.0f;
            if (m < 128)      v = slots[m * DIM_D + k0 + c];
            else if (m < MSP) v = pos[(m - 128) * DIM_D + k0 + c];
            sA[r * LDA + c] = wmma::__float_to_tf32(v);
        }
#pragma unroll
        for (int i = 0; i < 16; i++) {
            int e = i * 256 + tid;
            int r = e >> 7, c = e & 127;
            sB[r * LDB + c] = wmma::__float_to_tf32(W1[(k0 + r) * DIM_H + h0 + c]);
        }
        __syncthreads();

#pragma unroll
        for (int ks = 0; ks < BK; ks += 8) {
            wmma::fragment<wmma::matrix_a, 16, 16, 8, wmma::precision::tf32,
                           wmma::row_major> af[2];
            wmma::fragment<wmma::matrix_b, 16, 16, 8, wmma::precision::tf32,
                           wmma::row_major> bf[2];
#pragma unroll
            for (int i = 0; i < 2; i++)
                wmma::load_matrix_sync(af[i], &sA[(warp_m * 32 + i * 16) * LDA + ks], LDA);
#pragma unroll
            for (int j = 0; j < 2; j++)
                wmma::load_matrix_sync(bf[j], &sB[ks * LDB + warp_n * 32 + j * 16], LDB);
#pragma unroll
            for (int i = 0; i < 2; i++)
#pragma unroll
                for (int j = 0; j < 2; j++)
                    wmma::mma_sync(acc[i][j], af[i], bf[j], acc[i][j]);
        }
        __syncthreads();
    }

#pragma unroll
    for (int i = 0; i < 2; i++)
#pragma unroll
        for (int j = 0; j < 2; j++)
            wmma::store_matrix_sync(
                &g_SP1[(m0 + warp_m * 32 + i * 16) * DIM_H + h0 + warp_n * 32 + j * 16],
                acc[i][j], DIM_H, wmma::mem_row_major);
}

// ---------------------------------------------------------------------------
// Kernel 2: combine  G[b*196+n, h] = tf32( 0.125 * sum_k relu(S1[b,k,h] + P1[n,h] + b1[h]) )
// ---------------------------------------------------------------------------
__global__ __launch_bounds__(256) void combine_kernel(const float* __restrict__ b1)
{
    const int b  = blockIdx.z;
    const int h0 = blockIdx.y * 1024 + threadIdx.x * 4;
    const int n0 = blockIdx.x * 49;

    float4 s[8];
#pragma unroll
    for (int k = 0; k < 8; k++)
        s[k] = *(const float4*)&g_SP1[(b * 8 + k) * DIM_H + h0];
    float4 bb = *(const float4*)&b1[h0];
#pragma unroll
    for (int k = 0; k < 8; k++) {
        s[k].x += bb.x; s[k].y += bb.y; s[k].z += bb.z; s[k].w += bb.w;
    }

    for (int n = 0; n < 49; n++) {
        int nn = n0 + n;
        float4 p = *(const float4*)&g_SP1[(128 + nn) * DIM_H + h0];
        float4 a;
        a.x = a.y = a.z = a.w = 0.0f;
#pragma unroll
        for (int k = 0; k < 8; k++) {
            a.x += fmaxf(s[k].x + p.x, 0.0f);
            a.y += fmaxf(s[k].y + p.y, 0.0f);
            a.z += fmaxf(s[k].z + p.z, 0.0f);
            a.w += fmaxf(s[k].w + p.w, 0.0f);
        }
        a.x = wmma::__float_to_tf32(a.x * 0.125f);
        a.y = wmma::__float_to_tf32(a.y * 0.125f);
        a.z = wmma::__float_to_tf32(a.z * 0.125f);
        a.w = wmma::__float_to_tf32(a.w * 0.125f);
        *(float4*)&g_G[(b * DIM_N + nn) * DIM_H + h0] = a;
    }
}

// ---------------------------------------------------------------------------
// Pass 2: out(3136x768) = G(3200x3072 padded) @ W2c(3072x768) + b2
// BM=128 BN=128 BK=32, 256 threads (warp tile 64x32, acc 4x2),
// cp.async double-buffered, single wave (grid 150 on 148 SMs)
// ---------------------------------------------------------------------------
__global__ __launch_bounds__(256, 2) void pass2_kernel(
    const float* __restrict__ b2,
    float* __restrict__ out)
{
    constexpr int BM = 128, BN = 128, BK = 32;
    constexpr int LDA = 36, LDB = 136, LDC = 132;
    constexpr int ASZ = BM * LDA;   // 4608 floats
    constexpr int BSZ = BK * LDB;   // 4352 floats
    constexpr int KT  = DIM_H / BK; // 96

    extern __shared__ float smx[];
    float* As = smx;               // 2 * ASZ
    float* Bs = smx + 2 * ASZ;     // 2 * BSZ
    float* Cs = smx;               // epilogue reuse: 128*132 = 16896 <= 17920

    const int o0  = blockIdx.x * BN;
    const int m0  = blockIdx.y * BM;
    const int tid = threadIdx.x;
    const int wid = tid >> 5;
    const int warp_m = wid >> 2;   // 0..1 -> 64 rows
    const int warp_n = wid & 3;    // 0..3 -> 32 cols

    wmma::fragment<wmma::accumulator, 16, 16, 8, float> acc[4][2];
#pragma unroll
    for (int i = 0; i < 4; i++)
#pragma unroll
        for (int j = 0; j < 2; j++)
            wmma::fill_fragment(acc[i][j], 0.0f);

    const int ar0 = tid >> 3, ac4 = (tid & 7) * 4;
    const int br0 = tid >> 5, bc4 = (tid & 31) * 4;

#define LOAD_TILES(kt, buf)                                                         \
    {                                                                               \
        const float* gA = g_G + (size_t)m0 * DIM_H + (kt) * BK;                     \
        float* sA = As + (buf) * ASZ;                                               \
        cp16(sA + ar0 * LDA + ac4,        gA + (size_t)ar0 * DIM_H + ac4);          \
        cp16(sA + (ar0 + 32) * LDA + ac4, gA + (size_t)(ar0 + 32) * DIM_H + ac4);   \
        cp16(sA + (ar0 + 64) * LDA + ac4, gA + (size_t)(ar0 + 64) * DIM_H + ac4);   \
        cp16(sA + (ar0 + 96) * LDA + ac4, gA + (size_t)(ar0 + 96) * DIM_H + ac4);   \
        const float* gB = g_W2c + (size_t)(kt) * BK * DIM_DOUT + o0;                \
        float* sB = Bs + (buf) * BSZ;                                               \
        cp16(sB + br0 * LDB + bc4,        gB + (size_t)br0 * DIM_DOUT + bc4);       \
        cp16(sB + (br0 + 8) * LDB + bc4,  gB + (size_t)(br0 + 8) * DIM_DOUT + bc4); \
        cp16(sB + (br0 + 16) * LDB + bc4, gB + (size_t)(br0 + 16) * DIM_DOUT + bc4);\
        cp16(sB + (br0 + 24) * LDB + bc4, gB + (size_t)(br0 + 24) * DIM_DOUT + bc4);\
    }

    LOAD_TILES(0, 0);
    cp_commit();

    int buf = 0;
    for (int kt = 0; kt < KT; kt++) {
        cp_wait0();
        __syncthreads();
        if (kt + 1 < KT) {
            LOAD_TILES(kt + 1, buf ^ 1);
            cp_commit();
        }
        float* sA = As + buf * ASZ;
        float* sB = Bs + buf * BSZ;
#pragma unroll
        for (int ks = 0; ks < BK; ks += 8) {
            wmma::fragment<wmma::matrix_a, 16, 16, 8, wmma::precision::tf32,
                           wmma::row_major> af[4];
            wmma::fragment<wmma::matrix_b, 16, 16, 8, wmma::precision::tf32,
                           wmma::row_major> bf[2];
#pragma unroll
            for (int i = 0; i < 4; i++)
                wmma::load_matrix_sync(af[i], &sA[(warp_m * 64 + i * 16) * LDA + ks], LDA);
#pragma unroll
            for (int j = 0; j < 2; j++)
                wmma::load_matrix_sync(bf[j], &sB[ks * LDB + warp_n * 32 + j * 16], LDB);
#pragma unroll
            for (int i = 0; i < 4; i++)
#pragma unroll
                for (int j = 0; j < 2; j++)
                    wmma::mma_sync(acc[i][j], af[i], bf[j], acc[i][j]);
        }
        __syncthreads();
        buf ^= 1;
    }
#undef LOAD_TILES

    // epilogue via smem, add bias, write out (guard padded rows)
#pragma unroll
    for (int i = 0; i < 4; i++)
#pragma unroll
        for (int j = 0; j < 2; j++)
            wmma::store_matrix_sync(
                &Cs[(warp_m * 64 + i * 16) * LDC + warp_n * 32 + j * 16],
                acc[i][j], LDC, wmma::mem_row_major);
    __syncthreads();

    // 128 rows x 32 float4 = 4096 slots -> 16 iterations of 256 threads
#pragma unroll
    for (int p = 0; p < 16; p++) {
        int o = p * 256 + tid;
        int r = o >> 5, c4 = (o & 31) * 4;
        int m = m0 + r;
        if (m < M2) {
            float4 v = *(float4*)&Cs[r * LDC + c4];
            float4 bb = *(const float4*)&b2[o0 + c4];
            v.x += bb.x; v.y += bb.y; v.z += bb.z; v.w += bb.w;
            *(float4*)&out[(size_t)m * DIM_DOUT + o0 + c4] = v;
        }
    }
}

// ---------------------------------------------------------------------------
extern "C" void kernel_launch(void* const* d_in, const int* in_sizes, int n_in,
                              void* d_out, int out_size)
{
    const float* slots = (const float*)d_in[0];   // (16,8,768)
    const float* pos   = (const float*)d_in[1];   // (196,768)
    // d_in[2] = map_alpha : softmax over K of identical values == 1/8 exactly
    const float* W1    = (const float*)d_in[3];   // (768,3072)
    const float* b1    = (const float*)d_in[4];   // (3072,)
    const float* W2    = (const float*)d_in[5];   // (3072,768)
    const float* b2    = (const float*)d_in[6];   // (768,)
    float* out = (float*)d_out;                   // (16,196,768)

    // pass2 dynamic smem: 2*(4608+4352)*4 = 71680 bytes
    constexpr int P2_SMEM = 2 * (128 * 36 + 32 * 136) * 4;
    static_assert(P2_SMEM == 71680, "smem size");
    cudaFuncSetAttribute(pass2_kernel,
                         cudaFuncAttributeMaxDynamicSharedMemorySize, P2_SMEM);

    convw2_kernel<<<(DIM_H * DIM_DOUT) / 1024, 256>>>(W2);

    dim3 gs(DIM_H / 128, MSP_PAD / 64);             // (24, 6)
    gemm_small_kernel<<<gs, 256>>>(slots, pos, W1);

    dim3 gc(4, 3, DIM_B);                           // n-chunks, h-chunks, b
    combine_kernel<<<gc, 256>>>(b1);

    dim3 g2(DIM_DOUT / 128, M2_PAD / 128);          // (6, 25) = 150 blocks
    pass2_kernel<<<g2, 256, P2_SMEM>>>(b2, out);
}

// round 7
// speedup vs baseline: 14.9993x; 2.4278x over previous
#include <cuda_runtime.h>
#include <cuda_fp16.h>
#include <mma.h>
#include <cstdint>

using namespace nvcuda;

// Problem dims
#define DIM_B    16
#define DIM_K    8
#define DIM_N    196
#define DIM_D    768
#define DIM_H    3072
#define DIM_DOUT 768

#define M2      (DIM_B * DIM_N)   // 3136 reduced rows (b*196+n)
#define M2_PAD  3200              // padded to 64-multiple
#define MSP     324               // 128 slot rows + 196 pos rows
#define MSP_PAD 384               // padded to 64-multiple

// Scratch (zero-initialized at module load; padded G rows stay 0 forever)
__device__ float  g_SP1[MSP_PAD * DIM_H];    // fp32: slots@W1 (rows 0..127), pos@W1 (128..323)
__device__ __half g_Gh[M2_PAD * DIM_H];      // fp16 combined hidden (GEMM2 A)
__device__ __half g_W2h[DIM_H * DIM_DOUT];   // fp16 W2 (GEMM2 B)

// ---------------------------------------------------------------------------
// cp.async helpers
// ---------------------------------------------------------------------------
__device__ __forceinline__ void cp16u(unsigned saddr, const void* g) {
    asm volatile("cp.async.cg.shared.global [%0], [%1], 16;"
                 :: "r"(saddr), "l"(g));
}
__device__ __forceinline__ unsigned smem_u32(const void* p) {
    unsigned a;
    asm("{ .reg .u64 t; cvta.to.shared.u64 t, %1; cvt.u32.u64 %0, t; }"
        : "=r"(a) : "l"(p));
    return a;
}

// ---------------------------------------------------------------------------
// Kernel 0: convert W2 to fp16 (RN) once
// ---------------------------------------------------------------------------
__global__ void convw2_kernel(const float* __restrict__ W2) {
    int i = (blockIdx.x * 256 + threadIdx.x) * 4;
    float4 v = *(const float4*)&W2[i];
    __half2 h01 = __floats2half2_rn(v.x, v.y);
    __half2 h23 = __floats2half2_rn(v.z, v.w);
    uint2 u;
    u.x = *(unsigned*)&h01;
    u.y = *(unsigned*)&h23;
    *(uint2*)&g_W2h[i] = u;
}

// ---------------------------------------------------------------------------
// Kernel 1: tiny GEMM  [slots; pos] (324x768) @ W1 (768x3072) -> g_SP1 (fp32)
// fp16 operands, f32 accumulate. BM=64 BN=128 BK=32, 256 threads.
// ---------------------------------------------------------------------------
__global__ __launch_bounds__(256, 2) void gemm_small_kernel(
    const float* __restrict__ slots,
    const float* __restrict__ pos,
    const float* __restrict__ W1)
{
    constexpr int BM = 64, BN = 128, BK = 32;
    constexpr int LDA = 40, LDB = 136;   // halves

    __shared__ __half sA[BM * LDA];
    __shared__ __half sB[BK * LDB];

    const int h0  = blockIdx.x * BN;
    const int m0  = blockIdx.y * BM;
    const int tid = threadIdx.x;
    const int wid = tid >> 5;
    const int warp_m = wid >> 2;   // 0..1 -> 32 rows
    const int warp_n = wid & 3;    // 0..3 -> 32 cols

    wmma::fragment<wmma::accumulator, 16, 16, 16, float> acc[2][2];
#pragma unroll
    for (int i = 0; i < 2; i++)
#pragma unroll
        for (int j = 0; j < 2; j++)
            wmma::fill_fragment(acc[i][j], 0.0f);

    for (int k0 = 0; k0 < DIM_D; k0 += BK) {
        // A tile 64x32 (slots+pos computed in fp32, then RN to fp16)
#pragma unroll
        for (int i = 0; i < 8; i++) {
            int e = i * 256 + tid;
            int r = e >> 5, c = e & 31;
            int m = m0 + r;
            float v = 0.0f;
            if (m < 128)      v = slots[m * DIM_D + k0 + c];
            else if (m < MSP) v = pos[(m - 128) * DIM_D + k0 + c];
            sA[r * LDA + c] = __float2half_rn(v);
        }
        // B tile 32x128 from W1
#pragma unroll
        for (int i = 0; i < 16; i++) {
            int e = i * 256 + tid;
            int r = e >> 7, c = e & 127;
            sB[r * LDB + c] = __float2half_rn(W1[(k0 + r) * DIM_H + h0 + c]);
        }
        __syncthreads();

#pragma unroll
        for (int ks = 0; ks < BK; ks += 16) {
            wmma::fragment<wmma::matrix_a, 16, 16, 16, __half, wmma::row_major> af[2];
            wmma::fragment<wmma::matrix_b, 16, 16, 16, __half, wmma::row_major> bf[2];
#pragma unroll
            for (int i = 0; i < 2; i++)
                wmma::load_matrix_sync(af[i], &sA[(warp_m * 32 + i * 16) * LDA + ks], LDA);
#pragma unroll
            for (int j = 0; j < 2; j++)
                wmma::load_matrix_sync(bf[j], &sB[ks * LDB + warp_n * 32 + j * 16], LDB);
#pragma unroll
            for (int i = 0; i < 2; i++)
#pragma unroll
                for (int j = 0; j < 2; j++)
                    wmma::mma_sync(acc[i][j], af[i], bf[j], acc[i][j]);
        }
        __syncthreads();
    }

#pragma unroll
    for (int i = 0; i < 2; i++)
#pragma unroll
        for (int j = 0; j < 2; j++)
            wmma::store_matrix_sync(
                &g_SP1[(m0 + warp_m * 32 + i * 16) * DIM_H + h0 + warp_n * 32 + j * 16],
                acc[i][j], DIM_H, wmma::mem_row_major);
}

// ---------------------------------------------------------------------------
// Kernel 2: combine  Gh[b*196+n, h] = fp16( 0.125 * sum_k relu(S1[b,k,h]+P1[n,h]+b1[h]) )
// ---------------------------------------------------------------------------
__global__ __launch_bounds__(256) void combine_kernel(const float* __restrict__ b1)
{
    const int b  = blockIdx.z;
    const int h0 = blockIdx.y * 1024 + threadIdx.x * 4;
    const int n0 = blockIdx.x * 49;

    float4 s[8];
#pragma unroll
    for (int k = 0; k < 8; k++)
        s[k] = *(const float4*)&g_SP1[(b * 8 + k) * DIM_H + h0];
    float4 bb = *(const float4*)&b1[h0];
#pragma unroll
    for (int k = 0; k < 8; k++) {
        s[k].x += bb.x; s[k].y += bb.y; s[k].z += bb.z; s[k].w += bb.w;
    }

    for (int n = 0; n < 49; n++) {
        int nn = n0 + n;
        float4 p = *(const float4*)&g_SP1[(128 + nn) * DIM_H + h0];
        float4 a;
        a.x = a.y = a.z = a.w = 0.0f;
#pragma unroll
        for (int k = 0; k < 8; k++) {
            a.x += fmaxf(s[k].x + p.x, 0.0f);
            a.y += fmaxf(s[k].y + p.y, 0.0f);
            a.z += fmaxf(s[k].z + p.z, 0.0f);
            a.w += fmaxf(s[k].w + p.w, 0.0f);
        }
        __half2 h01 = __floats2half2_rn(a.x * 0.125f, a.y * 0.125f);
        __half2 h23 = __floats2half2_rn(a.z * 0.125f, a.w * 0.125f);
        uint2 u;
        u.x = *(unsigned*)&h01;
        u.y = *(unsigned*)&h23;
        *(uint2*)&g_Gh[(size_t)(b * DIM_N + nn) * DIM_H + h0] = u;
    }
}

// ---------------------------------------------------------------------------
// Pass 2 (fp16): out(3136x768) = Gh(3200x3072) @ W2h(3072x768) + b2
// BM=64 BN=128 BK=32, 256 threads, warp tile 32x32, cp.async double-buffered.
// grid (6,50)=300 CTAs, 2 CTAs/SM.
// ---------------------------------------------------------------------------
__global__ __launch_bounds__(256, 2) void pass2_kernel(
    const float* __restrict__ b2,
    float* __restrict__ out)
{
    constexpr int BM = 64, BN = 128, BK = 32;
    constexpr int LDA = 40, LDB = 136;       // halves
    constexpr int LDC = 132;                 // floats
    constexpr int ASZ = BM * LDA;            // 2560 halves
    constexpr int BSZ = BK * LDB;            // 4352 halves
    constexpr int KT  = DIM_H / BK;          // 96

    extern __shared__ __align__(16) char smraw[];
    __half* As = (__half*)smraw;             // 2 * ASZ halves
    __half* Bs = As + 2 * ASZ;               // 2 * BSZ halves
    float*  Cs = (float*)smraw;              // epilogue reuse: 64*132 f32 = 33792 B

    const unsigned sb = smem_u32(smraw);
    const unsigned sbB = sb + 2 * ASZ * 2;

    const int o0  = blockIdx.x * BN;
    const int m0  = blockIdx.y * BM;
    const int tid = threadIdx.x;
    const int wid = tid >> 5;
    const int warp_m = wid >> 2;   // 0..1
    const int warp_n = wid & 3;    // 0..3

    wmma::fragment<wmma::accumulator, 16, 16, 16, float> acc[2][2];
#pragma unroll
    for (int i = 0; i < 2; i++)
#pragma unroll
        for (int j = 0; j < 2; j++)
            wmma::fill_fragment(acc[i][j], 0.0f);

    // A: 64 rows x 32 halves (64B/row) = 256 cp16 -> 1/thread
    const int ar = tid >> 2, ac = (tid & 3) * 8;           // halves
    // B: 32 rows x 128 halves (256B/row) = 512 cp16 -> 2/thread (rows +16)
    const int br = tid >> 4, bc = (tid & 15) * 8;          // halves

    const __half* gA = g_Gh + (size_t)(m0 + ar) * DIM_H + ac;

#define LOAD_TILES(kt, st)                                                        \
    {                                                                             \
        cp16u(sb + (st) * ASZ * 2 + (ar * LDA + ac) * 2, gA + (kt) * BK);         \
        const __half* gB = g_W2h + (size_t)((kt) * BK + br) * DIM_DOUT + o0 + bc; \
        unsigned sB0 = sbB + (st) * BSZ * 2;                                      \
        cp16u(sB0 + (br * LDB + bc) * 2,        gB);                              \
        cp16u(sB0 + ((br + 16) * LDB + bc) * 2, gB + 16 * DIM_DOUT);              \
    }

    LOAD_TILES(0, 0);
    asm volatile("cp.async.commit_group;");

    int buf = 0;
    for (int kt = 0; kt < KT; kt++) {
        asm volatile("cp.async.wait_group 0;");
        __syncthreads();
        if (kt + 1 < KT) {
            LOAD_TILES(kt + 1, buf ^ 1);
            asm volatile("cp.async.commit_group;");
        }
        const __half* sA = As + buf * ASZ;
        const __half* sB = Bs + buf * BSZ;
#pragma unroll
        for (int ks = 0; ks < BK; ks += 16) {
            wmma::fragment<wmma::matrix_a, 16, 16, 16, __half, wmma::row_major> af[2];
            wmma::fragment<wmma::matrix_b, 16, 16, 16, __half, wmma::row_major> bf[2];
#pragma unroll
            for (int i = 0; i < 2; i++)
                wmma::load_matrix_sync(af[i], &sA[(warp_m * 32 + i * 16) * LDA + ks], LDA);
#pragma unroll
            for (int j = 0; j < 2; j++)
                wmma::load_matrix_sync(bf[j], &sB[ks * LDB + warp_n * 32 + j * 16], LDB);
#pragma unroll
            for (int i = 0; i < 2; i++)
#pragma unroll
                for (int j = 0; j < 2; j++)
                    wmma::mma_sync(acc[i][j], af[i], bf[j], acc[i][j]);
        }
        __syncthreads();
        buf ^= 1;
    }
#undef LOAD_TILES

    // epilogue via smem (reuses tile space), add bias, write out
#pragma unroll
    for (int i = 0; i < 2; i++)
#pragma unroll
        for (int j = 0; j < 2; j++)
            wmma::store_matrix_sync(
                &Cs[(warp_m * 32 + i * 16) * LDC + warp_n * 32 + j * 16],
                acc[i][j], LDC, wmma::mem_row_major);
    __syncthreads();

    // 64 rows x 32 float4 = 2048 slots -> 8 iterations
#pragma unroll
    for (int p = 0; p < 8; p++) {
        int o = p * 256 + tid;
        int r = o >> 5, c4 = (o & 31) * 4;
        int m = m0 + r;
        if (m < M2) {
            float4 v = *(float4*)&Cs[r * LDC + c4];
            float4 bb = *(const float4*)&b2[o0 + c4];
            v.x += bb.x; v.y += bb.y; v.z += bb.z; v.w += bb.w;
            *(float4*)&out[(size_t)m * DIM_DOUT + o0 + c4] = v;
        }
    }
}

// ---------------------------------------------------------------------------
extern "C" void kernel_launch(void* const* d_in, const int* in_sizes, int n_in,
                              void* d_out, int out_size)
{
    const float* slots = (const float*)d_in[0];   // (16,8,768)
    const float* pos   = (const float*)d_in[1];   // (196,768)
    // d_in[2] = map_alpha : softmax over K of identical values == 1/8 exactly
    const float* W1    = (const float*)d_in[3];   // (768,3072)
    const float* b1    = (const float*)d_in[4];   // (3072,)
    const float* W2    = (const float*)d_in[5];   // (3072,768)
    const float* b2    = (const float*)d_in[6];   // (768,)
    float* out = (float*)d_out;                   // (16,196,768)

    // pass2 dynamic smem: max(tiles 27648 B, epilogue 64*132*4 = 33792 B)
    constexpr int P2_SMEM = 64 * 132 * 4;  // 33792
    cudaFuncSetAttribute(pass2_kernel,
                         cudaFuncAttributeMaxDynamicSharedMemorySize, P2_SMEM);

    convw2_kernel<<<(DIM_H * DIM_DOUT) / 1024, 256>>>(W2);

    dim3 gs(DIM_H / 128, MSP_PAD / 64);             // (24, 6)
    gemm_small_kernel<<<gs, 256>>>(slots, pos, W1);

    dim3 gc(4, 3, DIM_B);                           // n-chunks, h-chunks, b
    combine_kernel<<<gc, 256>>>(b1);

    dim3 g2(DIM_DOUT / 128, M2_PAD / 64);           // (6, 50) = 300 blocks
    pass2_kernel<<<g2, 256, P2_SMEM>>>(b2, out);
}

// round 8
// speedup vs baseline: 22.2051x; 1.4804x over previous
#include <cuda_runtime.h>
#include <cuda_fp16.h>
#include <mma.h>
#include <cstdint>

using namespace nvcuda;

// Problem dims
#define DIM_B    16
#define DIM_K    8
#define DIM_N    196
#define DIM_D    768
#define DIM_H    3072
#define DIM_DOUT 768

#define M2      (DIM_B * DIM_N)   // 3136 reduced rows (b*196+n)
#define M2_PAD  3200              // padded to 64-multiple
#define MSP     324               // 128 slot rows + 196 pos rows
#define MSP_PAD 384               // padded to 64-multiple

// Scratch (zero-initialized at module load)
__device__ __half g_Ah[MSP_PAD * DIM_D];     // fp16 [slots;pos] (GEMM1 A)
__device__ __half g_W1h[DIM_D * DIM_H];      // fp16 W1 (GEMM1 B)
__device__ float  g_SP1[MSP_PAD * DIM_H];    // fp32: slots@W1 (0..127), pos@W1 (128..323)
__device__ __half g_Gh[M2_PAD * DIM_H];      // fp16 combined hidden (GEMM2 A)
__device__ __half g_W2h[DIM_H * DIM_DOUT];   // fp16 W2 (GEMM2 B)

// ---------------------------------------------------------------------------
// helpers
// ---------------------------------------------------------------------------
__device__ __forceinline__ void cp16u(unsigned saddr, const void* g) {
    asm volatile("cp.async.cg.shared.global [%0], [%1], 16;"
                 :: "r"(saddr), "l"(g));
}
__device__ __forceinline__ unsigned smem_u32(const void* p) {
    unsigned a;
    asm("{ .reg .u64 t; cvta.to.shared.u64 t, %1; cvt.u32.u64 %0, t; }"
        : "=r"(a) : "l"(p));
    return a;
}
__device__ __forceinline__ uint2 f4_to_h4(float4 v) {
    __half2 h01 = __floats2half2_rn(v.x, v.y);
    __half2 h23 = __floats2half2_rn(v.z, v.w);
    uint2 u;
    u.x = *(unsigned*)&h01;
    u.y = *(unsigned*)&h23;
    return u;
}

// ---------------------------------------------------------------------------
// Kernel 0: fused fp16 conversion of W1, W2, and [slots;pos]
// index space in float4 units: W1 (589824) | W2 (589824) | A (73728)
// ---------------------------------------------------------------------------
#define W1_F4 (DIM_D * DIM_H / 4)
#define W2_F4 (DIM_H * DIM_DOUT / 4)
#define A_F4  (MSP_PAD * DIM_D / 4)

__global__ __launch_bounds__(256) void conv_kernel(
    const float* __restrict__ W1,
    const float* __restrict__ W2,
    const float* __restrict__ slots,
    const float* __restrict__ pos)
{
    int i = blockIdx.x * 256 + threadIdx.x;
    if (i < W1_F4) {
        *(uint2*)&g_W1h[i * 4] = f4_to_h4(*(const float4*)&W1[i * 4]);
    } else if (i < W1_F4 + W2_F4) {
        int j = i - W1_F4;
        *(uint2*)&g_W2h[j * 4] = f4_to_h4(*(const float4*)&W2[j * 4]);
    } else if (i < W1_F4 + W2_F4 + A_F4) {
        int j = i - W1_F4 - W2_F4;           // float4 index within A
        int m = (j * 4) / DIM_D;
        int c = (j * 4) % DIM_D;
        float4 v = make_float4(0.f, 0.f, 0.f, 0.f);
        if (m < 128)      v = *(const float4*)&slots[m * DIM_D + c];
        else if (m < MSP) v = *(const float4*)&pos[(m - 128) * DIM_D + c];
        *(uint2*)&g_Ah[j * 4] = f4_to_h4(v);
    }
}

// ---------------------------------------------------------------------------
// Generic fp16 GEMM mainloop pieces (BM=64, BN=128, BK=64, 256 thr, 8 warps,
// warp tile 32x32, cp.async double-buffered)
// ---------------------------------------------------------------------------
#define LDA 72     // halves (64 + 8 pad)
#define LDB 136    // halves (128 + 8 pad)
#define ASZ (64 * LDA)
#define BSZ (64 * LDB)

// ---------------------------------------------------------------------------
// Kernel 1: GEMM1  g_Ah(384x768) @ g_W1h(768x3072) -> g_SP1 (fp32)
// grid (24, 6)
// ---------------------------------------------------------------------------
__global__ __launch_bounds__(256, 2) void gemm_small_kernel()
{
    constexpr int KT = DIM_D / 64;   // 12

    extern __shared__ __align__(16) char smraw[];
    __half* As = (__half*)smraw;
    __half* Bs = As + 2 * ASZ;
    const unsigned sb  = smem_u32(smraw);
    const unsigned sbB = sb + 2 * ASZ * 2;

    const int h0  = blockIdx.x * 128;
    const int m0  = blockIdx.y * 64;
    const int tid = threadIdx.x;
    const int wid = tid >> 5;
    const int warp_m = wid >> 2;
    const int warp_n = wid & 3;

    wmma::fragment<wmma::accumulator, 16, 16, 16, float> acc[2][2];
#pragma unroll
    for (int i = 0; i < 2; i++)
#pragma unroll
        for (int j = 0; j < 2; j++)
            wmma::fill_fragment(acc[i][j], 0.0f);

    // A: 64 rows x 64 halves (128B/row) = 512 cp16 -> 2/thread
    const int ar = tid >> 2, ac = (tid & 3) * 8;
    // B: 64 rows x 128 halves (256B/row) = 1024 cp16 -> 4/thread
    const int br = tid >> 4, bc = (tid & 15) * 8;

    const __half* gA = g_Ah + (size_t)(m0 + ar) * DIM_D + ac;

#define LOAD1(kt, st)                                                             \
    {                                                                             \
        unsigned sA0 = sb + (st) * ASZ * 2;                                       \
        cp16u(sA0 + (ar * LDA + ac) * 2,        gA + (kt) * 64);                  \
        cp16u(sA0 + (ar * LDA + ac + 32) * 2,   gA + (kt) * 64 + 32);             \
        const __half* gB = g_W1h + (size_t)((kt) * 64 + br) * DIM_H + h0 + bc;    \
        unsigned sB0 = sbB + (st) * BSZ * 2;                                      \
        cp16u(sB0 + (br * LDB + bc) * 2,        gB);                              \
        cp16u(sB0 + ((br + 16) * LDB + bc) * 2, gB + (size_t)16 * DIM_H);         \
        cp16u(sB0 + ((br + 32) * LDB + bc) * 2, gB + (size_t)32 * DIM_H);         \
        cp16u(sB0 + ((br + 48) * LDB + bc) * 2, gB + (size_t)48 * DIM_H);         \
    }

    LOAD1(0, 0);
    asm volatile("cp.async.commit_group;");

    int buf = 0;
    for (int kt = 0; kt < KT; kt++) {
        asm volatile("cp.async.wait_group 0;");
        __syncthreads();
        if (kt + 1 < KT) {
            LOAD1(kt + 1, buf ^ 1);
            asm volatile("cp.async.commit_group;");
        }
        const __half* sA = As + buf * ASZ;
        const __half* sB = Bs + buf * BSZ;
#pragma unroll
        for (int ks = 0; ks < 64; ks += 16) {
            wmma::fragment<wmma::matrix_a, 16, 16, 16, __half, wmma::row_major> af[2];
            wmma::fragment<wmma::matrix_b, 16, 16, 16, __half, wmma::row_major> bf[2];
#pragma unroll
            for (int i = 0; i < 2; i++)
                wmma::load_matrix_sync(af[i], &sA[(warp_m * 32 + i * 16) * LDA + ks], LDA);
#pragma unroll
            for (int j = 0; j < 2; j++)
                wmma::load_matrix_sync(bf[j], &sB[ks * LDB + warp_n * 32 + j * 16], LDB);
#pragma unroll
            for (int i = 0; i < 2; i++)
#pragma unroll
                for (int j = 0; j < 2; j++)
                    wmma::mma_sync(acc[i][j], af[i], bf[j], acc[i][j]);
        }
        __syncthreads();
        buf ^= 1;
    }
#undef LOAD1

#pragma unroll
    for (int i = 0; i < 2; i++)
#pragma unroll
        for (int j = 0; j < 2; j++)
            wmma::store_matrix_sync(
                &g_SP1[(size_t)(m0 + warp_m * 32 + i * 16) * DIM_H + h0 + warp_n * 32 + j * 16],
                acc[i][j], DIM_H, wmma::mem_row_major);
}

// ---------------------------------------------------------------------------
// Kernel 2: combine  Gh[b*196+n, h] = fp16( 0.125 * sum_k relu(S1[b,k,h]+P1[n,h]+b1[h]) )
// ---------------------------------------------------------------------------
__global__ __launch_bounds__(256) void combine_kernel(const float* __restrict__ b1)
{
    const int b  = blockIdx.z;
    const int h0 = blockIdx.y * 1024 + threadIdx.x * 4;
    const int n0 = blockIdx.x * 49;

    float4 s[8];
#pragma unroll
    for (int k = 0; k < 8; k++)
        s[k] = *(const float4*)&g_SP1[(size_t)(b * 8 + k) * DIM_H + h0];
    float4 bb = *(const float4*)&b1[h0];
#pragma unroll
    for (int k = 0; k < 8; k++) {
        s[k].x += bb.x; s[k].y += bb.y; s[k].z += bb.z; s[k].w += bb.w;
    }

    for (int n = 0; n < 49; n++) {
        int nn = n0 + n;
        float4 p = *(const float4*)&g_SP1[(size_t)(128 + nn) * DIM_H + h0];
        float4 a;
        a.x = a.y = a.z = a.w = 0.0f;
#pragma unroll
        for (int k = 0; k < 8; k++) {
            a.x += fmaxf(s[k].x + p.x, 0.0f);
            a.y += fmaxf(s[k].y + p.y, 0.0f);
            a.z += fmaxf(s[k].z + p.z, 0.0f);
            a.w += fmaxf(s[k].w + p.w, 0.0f);
        }
        a.x *= 0.125f; a.y *= 0.125f; a.z *= 0.125f; a.w *= 0.125f;
        *(uint2*)&g_Gh[(size_t)(b * DIM_N + nn) * DIM_H + h0] = f4_to_h4(a);
    }
}

// ---------------------------------------------------------------------------
// Pass 2 (fp16): out(3136x768) = Gh(3200x3072) @ W2h(3072x768) + b2
// BM=64 BN=128 BK=64, grid (6,50)=300 CTAs, 2 CTAs/SM.
// ---------------------------------------------------------------------------
__global__ __launch_bounds__(256, 2) void pass2_kernel(
    const float* __restrict__ b2,
    float* __restrict__ out)
{
    constexpr int KT  = DIM_H / 64;   // 48
    constexpr int LDC = 132;          // floats

    extern __shared__ __align__(16) char smraw[];
    __half* As = (__half*)smraw;
    __half* Bs = As + 2 * ASZ;
    float*  Cs = (float*)smraw;       // epilogue reuse: 64*132*4 = 33792 B

    const unsigned sb  = smem_u32(smraw);
    const unsigned sbB = sb + 2 * ASZ * 2;

    const int o0  = blockIdx.x * 128;
    const int m0  = blockIdx.y * 64;
    const int tid = threadIdx.x;
    const int wid = tid >> 5;
    const int warp_m = wid >> 2;
    const int warp_n = wid & 3;

    wmma::fragment<wmma::accumulator, 16, 16, 16, float> acc[2][2];
#pragma unroll
    for (int i = 0; i < 2; i++)
#pragma unroll
        for (int j = 0; j < 2; j++)
            wmma::fill_fragment(acc[i][j], 0.0f);

    const int ar = tid >> 2, ac = (tid & 3) * 8;
    const int br = tid >> 4, bc = (tid & 15) * 8;

    const __half* gA = g_Gh + (size_t)(m0 + ar) * DIM_H + ac;

#define LOAD2(kt, st)                                                             \
    {                                                                             \
        unsigned sA0 = sb + (st) * ASZ * 2;                                       \
        cp16u(sA0 + (ar * LDA + ac) * 2,        gA + (kt) * 64);                  \
        cp16u(sA0 + (ar * LDA + ac + 32) * 2,   gA + (kt) * 64 + 32);             \
        const __half* gB = g_W2h + (size_t)((kt) * 64 + br) * DIM_DOUT + o0 + bc; \
        unsigned sB0 = sbB + (st) * BSZ * 2;                                      \
        cp16u(sB0 + (br * LDB + bc) * 2,        gB);                              \
        cp16u(sB0 + ((br + 16) * LDB + bc) * 2, gB + 16 * DIM_DOUT);              \
        cp16u(sB0 + ((br + 32) * LDB + bc) * 2, gB + 32 * DIM_DOUT);              \
        cp16u(sB0 + ((br + 48) * LDB + bc) * 2, gB + 48 * DIM_DOUT);              \
    }

    LOAD2(0, 0);
    asm volatile("cp.async.commit_group;");

    int buf = 0;
    for (int kt = 0; kt < KT; kt++) {
        asm volatile("cp.async.wait_group 0;");
        __syncthreads();
        if (kt + 1 < KT) {
            LOAD2(kt + 1, buf ^ 1);
            asm volatile("cp.async.commit_group;");
        }
        const __half* sA = As + buf * ASZ;
        const __half* sB = Bs + buf * BSZ;
#pragma unroll
        for (int ks = 0; ks < 64; ks += 16) {
            wmma::fragment<wmma::matrix_a, 16, 16, 16, __half, wmma::row_major> af[2];
            wmma::fragment<wmma::matrix_b, 16, 16, 16, __half, wmma::row_major> bf[2];
#pragma unroll
            for (int i = 0; i < 2; i++)
                wmma::load_matrix_sync(af[i], &sA[(warp_m * 32 + i * 16) * LDA + ks], LDA);
#pragma unroll
            for (int j = 0; j < 2; j++)
                wmma::load_matrix_sync(bf[j], &sB[ks * LDB + warp_n * 32 + j * 16], LDB);
#pragma unroll
            for (int i = 0; i < 2; i++)
#pragma unroll
                for (int j = 0; j < 2; j++)
                    wmma::mma_sync(acc[i][j], af[i], bf[j], acc[i][j]);
        }
        __syncthreads();
        buf ^= 1;
    }
#undef LOAD2

    // epilogue via smem (reuses tile space), add bias, write out
#pragma unroll
    for (int i = 0; i < 2; i++)
#pragma unroll
        for (int j = 0; j < 2; j++)
            wmma::store_matrix_sync(
                &Cs[(warp_m * 32 + i * 16) * LDC + warp_n * 32 + j * 16],
                acc[i][j], LDC, wmma::mem_row_major);
    __syncthreads();

#pragma unroll
    for (int p = 0; p < 8; p++) {
        int o = p * 256 + tid;
        int r = o >> 5, c4 = (o & 31) * 4;
        int m = m0 + r;
        if (m < M2) {
            float4 v = *(float4*)&Cs[r * LDC + c4];
            float4 bb = *(const float4*)&b2[o0 + c4];
            v.x += bb.x; v.y += bb.y; v.z += bb.z; v.w += bb.w;
            *(float4*)&out[(size_t)m * DIM_DOUT + o0 + c4] = v;
        }
    }
}

// ---------------------------------------------------------------------------
extern "C" void kernel_launch(void* const* d_in, const int* in_sizes, int n_in,
                              void* d_out, int out_size)
{
    const float* slots = (const float*)d_in[0];   // (16,8,768)
    const float* pos   = (const float*)d_in[1];   // (196,768)
    // d_in[2] = map_alpha : softmax over K of identical values == 1/8 exactly
    const float* W1    = (const float*)d_in[3];   // (768,3072)
    const float* b1    = (const float*)d_in[4];   // (3072,)
    const float* W2    = (const float*)d_in[5];   // (3072,768)
    const float* b2    = (const float*)d_in[6];   // (768,)
    float* out = (float*)d_out;                   // (16,196,768)

    // dynamic smem for both GEMMs: 2*(ASZ+BSZ)*2 = 53248 B (> 48KB opt-in)
    constexpr int GSMEM = 2 * (ASZ + BSZ) * 2;
    static_assert(GSMEM == 53248, "smem");
    cudaFuncSetAttribute(gemm_small_kernel,
                         cudaFuncAttributeMaxDynamicSharedMemorySize, GSMEM);
    cudaFuncSetAttribute(pass2_kernel,
                         cudaFuncAttributeMaxDynamicSharedMemorySize, GSMEM);

    constexpr int CONV_BLKS = (W1_F4 + W2_F4 + A_F4 + 255) / 256;
    conv_kernel<<<CONV_BLKS, 256>>>(W1, W2, slots, pos);

    dim3 gs(DIM_H / 128, MSP_PAD / 64);             // (24, 6)
    gemm_small_kernel<<<gs, 256, GSMEM>>>();

    dim3 gc(4, 3, DIM_B);                           // n-chunks, h-chunks, b
    combine_kernel<<<gc, 256>>>(b1);

    dim3 g2(DIM_DOUT / 128, M2_PAD / 64);           // (6, 50) = 300 blocks
    pass2_kernel<<<g2, 256, GSMEM>>>(b2, out);
}

// round 9
// speedup vs baseline: 23.3630x; 1.0521x over previous
#include <cuda_runtime.h>
#include <cuda_fp16.h>
#include <mma.h>
#include <cstdint>

using namespace nvcuda;

// Problem dims
#define DIM_B    16
#define DIM_K    8
#define DIM_N    196
#define DIM_D    768
#define DIM_H    3072
#define DIM_DOUT 768

#define M2      (DIM_B * DIM_N)   // 3136 reduced rows (b*196+n)
#define M2_PAD  3200              // padded to 128-multiple (25*128)
#define MSP     324               // 128 slot rows + 196 pos rows
#define MSP_PAD 384               // padded to 64-multiple

// Scratch (zero-initialized at module load)
__device__ __half g_Ah[MSP_PAD * DIM_D];     // fp16 [slots;pos] (GEMM1 A)
__device__ __half g_W1h[DIM_D * DIM_H];      // fp16 W1 (GEMM1 B)
__device__ float  g_SP1[MSP_PAD * DIM_H];    // fp32: slots@W1 (0..127), pos@W1 (128..323)
__device__ __half g_Gh[M2_PAD * DIM_H];      // fp16 combined hidden (GEMM2 A)
__device__ __half g_W2h[DIM_H * DIM_DOUT];   // fp16 W2 (GEMM2 B)

// ---------------------------------------------------------------------------
// helpers
// ---------------------------------------------------------------------------
__device__ __forceinline__ void cp16u(unsigned saddr, const void* g) {
    asm volatile("cp.async.cg.shared.global [%0], [%1], 16;"
                 :: "r"(saddr), "l"(g));
}
__device__ __forceinline__ unsigned smem_u32(const void* p) {
    unsigned a;
    asm("{ .reg .u64 t; cvta.to.shared.u64 t, %1; cvt.u32.u64 %0, t; }"
        : "=r"(a) : "l"(p));
    return a;
}
__device__ __forceinline__ uint2 f4_to_h4(float4 v) {
    __half2 h01 = __floats2half2_rn(v.x, v.y);
    __half2 h23 = __floats2half2_rn(v.z, v.w);
    uint2 u;
    u.x = *(unsigned*)&h01;
    u.y = *(unsigned*)&h23;
    return u;
}

// ---------------------------------------------------------------------------
// Kernel 0: fused fp16 conversion of W1, W2, and [slots;pos]
// ---------------------------------------------------------------------------
#define W1_F4 (DIM_D * DIM_H / 4)
#define W2_F4 (DIM_H * DIM_DOUT / 4)
#define A_F4  (MSP_PAD * DIM_D / 4)

__global__ __launch_bounds__(256) void conv_kernel(
    const float* __restrict__ W1,
    const float* __restrict__ W2,
    const float* __restrict__ slots,
    const float* __restrict__ pos)
{
    int i = blockIdx.x * 256 + threadIdx.x;
    if (i < W1_F4) {
        *(uint2*)&g_W1h[i * 4] = f4_to_h4(*(const float4*)&W1[i * 4]);
    } else if (i < W1_F4 + W2_F4) {
        int j = i - W1_F4;
        *(uint2*)&g_W2h[j * 4] = f4_to_h4(*(const float4*)&W2[j * 4]);
    } else if (i < W1_F4 + W2_F4 + A_F4) {
        int j = i - W1_F4 - W2_F4;
        int m = (j * 4) / DIM_D;
        int c = (j * 4) % DIM_D;
        float4 v = make_float4(0.f, 0.f, 0.f, 0.f);
        if (m < 128)      v = *(const float4*)&slots[m * DIM_D + c];
        else if (m < MSP) v = *(const float4*)&pos[(m - 128) * DIM_D + c];
        *(uint2*)&g_Ah[j * 4] = f4_to_h4(v);
    }
}

#define LDA 72     // halves (64 + 8 pad)
#define LDB 136    // halves (128 + 8 pad)

// ---------------------------------------------------------------------------
// Kernel 1: GEMM1  g_Ah(384x768) @ g_W1h(768x3072) -> g_SP1 (fp32)
// BM=64 BN=128 BK=64, 256 thr, warp 32x32, double-buffered. grid (24,6)
// ---------------------------------------------------------------------------
__global__ __launch_bounds__(256, 2) void gemm_small_kernel()
{
    constexpr int KT  = DIM_D / 64;   // 12
    constexpr int ASZ = 64 * LDA;
    constexpr int BSZ = 64 * LDB;

    extern __shared__ __align__(16) char smraw[];
    __half* As = (__half*)smraw;
    __half* Bs = As + 2 * ASZ;
    const unsigned sb  = smem_u32(smraw);
    const unsigned sbB = sb + 2 * ASZ * 2;

    const int h0  = blockIdx.x * 128;
    const int m0  = blockIdx.y * 64;
    const int tid = threadIdx.x;
    const int wid = tid >> 5;
    const int warp_m = wid >> 2;
    const int warp_n = wid & 3;

    wmma::fragment<wmma::accumulator, 16, 16, 16, float> acc[2][2];
#pragma unroll
    for (int i = 0; i < 2; i++)
#pragma unroll
        for (int j = 0; j < 2; j++)
            wmma::fill_fragment(acc[i][j], 0.0f);

    const int ar = tid >> 2, ac = (tid & 3) * 8;
    const int br = tid >> 4, bc = (tid & 15) * 8;

    const __half* gA = g_Ah + (size_t)(m0 + ar) * DIM_D + ac;

#define LOAD1(kt, st)                                                             \
    {                                                                             \
        unsigned sA0 = sb + (st) * ASZ * 2;                                       \
        cp16u(sA0 + (ar * LDA + ac) * 2,        gA + (kt) * 64);                  \
        cp16u(sA0 + (ar * LDA + ac + 32) * 2,   gA + (kt) * 64 + 32);             \
        const __half* gB = g_W1h + (size_t)((kt) * 64 + br) * DIM_H + h0 + bc;    \
        unsigned sB0 = sbB + (st) * BSZ * 2;                                      \
        cp16u(sB0 + (br * LDB + bc) * 2,        gB);                              \
        cp16u(sB0 + ((br + 16) * LDB + bc) * 2, gB + (size_t)16 * DIM_H);         \
        cp16u(sB0 + ((br + 32) * LDB + bc) * 2, gB + (size_t)32 * DIM_H);         \
        cp16u(sB0 + ((br + 48) * LDB + bc) * 2, gB + (size_t)48 * DIM_H);         \
    }

    LOAD1(0, 0);
    asm volatile("cp.async.commit_group;");

    int buf = 0;
    for (int kt = 0; kt < KT; kt++) {
        asm volatile("cp.async.wait_group 0;");
        __syncthreads();
        if (kt + 1 < KT) {
            LOAD1(kt + 1, buf ^ 1);
            asm volatile("cp.async.commit_group;");
        }
        const __half* sA = As + buf * ASZ;
        const __half* sB = Bs + buf * BSZ;
#pragma unroll
        for (int ks = 0; ks < 64; ks += 16) {
            wmma::fragment<wmma::matrix_a, 16, 16, 16, __half, wmma::row_major> af[2];
            wmma::fragment<wmma::matrix_b, 16, 16, 16, __half, wmma::row_major> bf[2];
#pragma unroll
            for (int i = 0; i < 2; i++)
                wmma::load_matrix_sync(af[i], &sA[(warp_m * 32 + i * 16) * LDA + ks], LDA);
#pragma unroll
            for (int j = 0; j < 2; j++)
                wmma::load_matrix_sync(bf[j], &sB[ks * LDB + warp_n * 32 + j * 16], LDB);
#pragma unroll
            for (int i = 0; i < 2; i++)
#pragma unroll
                for (int j = 0; j < 2; j++)
                    wmma::mma_sync(acc[i][j], af[i], bf[j], acc[i][j]);
        }
        __syncthreads();
        buf ^= 1;
    }
#undef LOAD1

#pragma unroll
    for (int i = 0; i < 2; i++)
#pragma unroll
        for (int j = 0; j < 2; j++)
            wmma::store_matrix_sync(
                &g_SP1[(size_t)(m0 + warp_m * 32 + i * 16) * DIM_H + h0 + warp_n * 32 + j * 16],
                acc[i][j], DIM_H, wmma::mem_row_major);
}

// ---------------------------------------------------------------------------
// Kernel 2: combine  Gh[b*196+n, h] = fp16( 0.125 * sum_k relu(S1[b,k,h]+P1[n,h]+b1[h]) )
// grid (14 n-chunks, 3 h-chunks, 16 b) = 672 blocks, 14 n per block
// ---------------------------------------------------------------------------
__global__ __launch_bounds__(256) void combine_kernel(const float* __restrict__ b1)
{
    const int b  = blockIdx.z;
    const int h0 = blockIdx.y * 1024 + threadIdx.x * 4;
    const int n0 = blockIdx.x * 14;

    float4 s[8];
#pragma unroll
    for (int k = 0; k < 8; k++)
        s[k] = *(const float4*)&g_SP1[(size_t)(b * 8 + k) * DIM_H + h0];
    float4 bb = *(const float4*)&b1[h0];
#pragma unroll
    for (int k = 0; k < 8; k++) {
        s[k].x += bb.x; s[k].y += bb.y; s[k].z += bb.z; s[k].w += bb.w;
    }

#pragma unroll 2
    for (int n = 0; n < 14; n++) {
        int nn = n0 + n;
        float4 p = *(const float4*)&g_SP1[(size_t)(128 + nn) * DIM_H + h0];
        float4 a;
        a.x = a.y = a.z = a.w = 0.0f;
#pragma unroll
        for (int k = 0; k < 8; k++) {
            a.x += fmaxf(s[k].x + p.x, 0.0f);
            a.y += fmaxf(s[k].y + p.y, 0.0f);
            a.z += fmaxf(s[k].z + p.z, 0.0f);
            a.w += fmaxf(s[k].w + p.w, 0.0f);
        }
        a.x *= 0.125f; a.y *= 0.125f; a.z *= 0.125f; a.w *= 0.125f;
        *(uint2*)&g_Gh[(size_t)(b * DIM_N + nn) * DIM_H + h0] = f4_to_h4(a);
    }
}

// ---------------------------------------------------------------------------
// Pass 2 (fp16): out(3136x768) = Gh(3200x3072) @ W2h(3072x768) + b2
// BM=128 BN=128 BK=64, 256 thr (8 warps, warp tile 64x32, acc 4x2),
// double-buffered. grid (6,25)=150 CTAs = 1 wave.
// ---------------------------------------------------------------------------
__global__ __launch_bounds__(256) void pass2_kernel(
    const float* __restrict__ b2,
    float* __restrict__ out)
{
    constexpr int KT  = DIM_H / 64;   // 48
    constexpr int LDC = 132;          // floats
    constexpr int ASZ = 128 * LDA;    // 9216 halves
    constexpr int BSZ = 64 * LDB;     // 8704 halves

    extern __shared__ __align__(16) char smraw[];
    __half* As = (__half*)smraw;
    __half* Bs = As + 2 * ASZ;
    float*  Cs = (float*)smraw;       // epilogue reuse: 128*132*4 = 67584 B <= 71680

    const unsigned sb  = smem_u32(smraw);
    const unsigned sbB = sb + 2 * ASZ * 2;

    const int o0  = blockIdx.x * 128;
    const int m0  = blockIdx.y * 128;
    const int tid = threadIdx.x;
    const int wid = tid >> 5;
    const int warp_m = wid >> 2;   // 0..1 -> 64 rows
    const int warp_n = wid & 3;    // 0..3 -> 32 cols

    wmma::fragment<wmma::accumulator, 16, 16, 16, float> acc[4][2];
#pragma unroll
    for (int i = 0; i < 4; i++)
#pragma unroll
        for (int j = 0; j < 2; j++)
            wmma::fill_fragment(acc[i][j], 0.0f);

    // A: 128 rows x 64 halves (128B/row) = 1024 cp16, 4/thread: 2 thr/row
    const int ar = tid >> 1, ac = (tid & 1) * 32;
    // B: 64 rows x 128 halves (256B/row) = 1024 cp16, 4/thread (rows +16)
    const int br = tid >> 4, bc = (tid & 15) * 8;

    const __half* gA = g_Gh + (size_t)(m0 + ar) * DIM_H + ac;

#define LOAD2(kt, st)                                                             \
    {                                                                             \
        unsigned sA0 = sb + (st) * ASZ * 2 + (ar * LDA + ac) * 2;                 \
        const __half* a_ = gA + (kt) * 64;                                        \
        cp16u(sA0,      a_);                                                      \
        cp16u(sA0 + 16, a_ + 8);                                                  \
        cp16u(sA0 + 32, a_ + 16);                                                 \
        cp16u(sA0 + 48, a_ + 24);                                                 \
        const __half* gB = g_W2h + (size_t)((kt) * 64 + br) * DIM_DOUT + o0 + bc; \
        unsigned sB0 = sbB + (st) * BSZ * 2;                                      \
        cp16u(sB0 + (br * LDB + bc) * 2,        gB);                              \
        cp16u(sB0 + ((br + 16) * LDB + bc) * 2, gB + 16 * DIM_DOUT);              \
        cp16u(sB0 + ((br + 32) * LDB + bc) * 2, gB + 32 * DIM_DOUT);              \
        cp16u(sB0 + ((br + 48) * LDB + bc) * 2, gB + 48 * DIM_DOUT);              \
    }

    LOAD2(0, 0);
    asm volatile("cp.async.commit_group;");

    int buf = 0;
    for (int kt = 0; kt < KT; kt++) {
        asm volatile("cp.async.wait_group 0;");
        __syncthreads();
        if (kt + 1 < KT) {
            LOAD2(kt + 1, buf ^ 1);
            asm volatile("cp.async.commit_group;");
        }
        const __half* sA = As + buf * ASZ;
        const __half* sB = Bs + buf * BSZ;
#pragma unroll
        for (int ks = 0; ks < 64; ks += 16) {
            wmma::fragment<wmma::matrix_a, 16, 16, 16, __half, wmma::row_major> af[4];
            wmma::fragment<wmma::matrix_b, 16, 16, 16, __half, wmma::row_major> bf[2];
#pragma unroll
            for (int i = 0; i < 4; i++)
                wmma::load_matrix_sync(af[i], &sA[(warp_m * 64 + i * 16) * LDA + ks], LDA);
#pragma unroll
            for (int j = 0; j < 2; j++)
                wmma::load_matrix_sync(bf[j], &sB[ks * LDB + warp_n * 32 + j * 16], LDB);
#pragma unroll
            for (int i = 0; i < 4; i++)
#pragma unroll
                for (int j = 0; j < 2; j++)
                    wmma::mma_sync(acc[i][j], af[i], bf[j], acc[i][j]);
        }
        __syncthreads();
        buf ^= 1;
    }
#undef LOAD2

    // epilogue via smem (reuses tile space), add bias, write out
#pragma unroll
    for (int i = 0; i < 4; i++)
#pragma unroll
        for (int j = 0; j < 2; j++)
            wmma::store_matrix_sync(
                &Cs[(warp_m * 64 + i * 16) * LDC + warp_n * 32 + j * 16],
                acc[i][j], LDC, wmma::mem_row_major);
    __syncthreads();

    // 128 rows x 32 float4 = 4096 slots -> 16 iterations
#pragma unroll
    for (int p = 0; p < 16; p++) {
        int o = p * 256 + tid;
        int r = o >> 5, c4 = (o & 31) * 4;
        int m = m0 + r;
        if (m < M2) {
            float4 v = *(float4*)&Cs[r * LDC + c4];
            float4 bb = *(const float4*)&b2[o0 + c4];
            v.x += bb.x; v.y += bb.y; v.z += bb.z; v.w += bb.w;
            *(float4*)&out[(size_t)m * DIM_DOUT + o0 + c4] = v;
        }
    }
}

// ---------------------------------------------------------------------------
extern "C" void kernel_launch(void* const* d_in, const int* in_sizes, int n_in,
                              void* d_out, int out_size)
{
    const float* slots = (const float*)d_in[0];   // (16,8,768)
    const float* pos   = (const float*)d_in[1];   // (196,768)
    // d_in[2] = map_alpha : softmax over K of identical values == 1/8 exactly
    const float* W1    = (const float*)d_in[3];   // (768,3072)
    const float* b1    = (const float*)d_in[4];   // (3072,)
    const float* W2    = (const float*)d_in[5];   // (3072,768)
    const float* b2    = (const float*)d_in[6];   // (768,)
    float* out = (float*)d_out;                   // (16,196,768)

    constexpr int G1_SMEM = 2 * (64 * LDA + 64 * LDB) * 2;    // 53248
    constexpr int P2_SMEM = 2 * (128 * LDA + 64 * LDB) * 2;   // 71680
    cudaFuncSetAttribute(gemm_small_kernel,
                         cudaFuncAttributeMaxDynamicSharedMemorySize, G1_SMEM);
    cudaFuncSetAttribute(pass2_kernel,
                         cudaFuncAttributeMaxDynamicSharedMemorySize, P2_SMEM);

    constexpr int CONV_BLKS = (W1_F4 + W2_F4 + A_F4 + 255) / 256;
    conv_kernel<<<CONV_BLKS, 256>>>(W1, W2, slots, pos);

    dim3 gs(DIM_H / 128, MSP_PAD / 64);             // (24, 6)
    gemm_small_kernel<<<gs, 256, G1_SMEM>>>();

    dim3 gc(14, 3, DIM_B);                          // (14,3,16) = 672 blocks
    combine_kernel<<<gc, 256>>>(b1);

    dim3 g2(DIM_DOUT / 128, M2_PAD / 128);          // (6, 25) = 150 blocks
    pass2_kernel<<<g2, 256, P2_SMEM>>>(b2, out);
}

// round 10
// speedup vs baseline: 25.3596x; 1.0855x over previous
#include <cuda_runtime.h>
#include <cuda_fp16.h>
#include <mma.h>
#include <cstdint>

using namespace nvcuda;

// Problem dims
#define DIM_B    16
#define DIM_K    8
#define DIM_N    196
#define DIM_D    768
#define DIM_H    3072
#define DIM_DOUT 768

#define M2      (DIM_B * DIM_N)   // 3136 reduced rows (b*196+n)
#define M2_PAD  3200              // padded
#define MSP     324               // 128 slot rows + 196 pos rows
#define MSP_PAD 384

// Scratch (zero-initialized at module load)
__device__ __half g_Ah[MSP_PAD * DIM_D];     // fp16 [slots;pos] (GEMM1 A)
__device__ __half g_W1h[DIM_D * DIM_H];      // fp16 W1 (GEMM1 B)
__device__ float  g_SP1[MSP_PAD * DIM_H];    // fp32: slots@W1 (0..127), pos@W1 (128..323)
__device__ __half g_Gh[M2_PAD * DIM_H];      // fp16 combined hidden (GEMM2 A)
__device__ __half g_W2h[DIM_H * DIM_DOUT];   // fp16 W2 (GEMM2 B)

// ---------------------------------------------------------------------------
// helpers
// ---------------------------------------------------------------------------
__device__ __forceinline__ void cp16u(unsigned saddr, const void* g) {
    asm volatile("cp.async.cg.shared.global [%0], [%1], 16;"
                 :: "r"(saddr), "l"(g));
}
__device__ __forceinline__ unsigned smem_u32(const void* p) {
    unsigned a;
    asm("{ .reg .u64 t; cvta.to.shared.u64 t, %1; cvt.u32.u64 %0, t; }"
        : "=r"(a) : "l"(p));
    return a;
}
__device__ __forceinline__ uint2 f4_to_h4(float4 v) {
    __half2 h01 = __floats2half2_rn(v.x, v.y);
    __half2 h23 = __floats2half2_rn(v.z, v.w);
    uint2 u;
    u.x = *(unsigned*)&h01;
    u.y = *(unsigned*)&h23;
    return u;
}

// ---------------------------------------------------------------------------
// Kernel 0: fused fp16 conversion of W1, W2, and [slots;pos]
// ---------------------------------------------------------------------------
#define W1_F4 (DIM_D * DIM_H / 4)
#define W2_F4 (DIM_H * DIM_DOUT / 4)
#define A_F4  (MSP_PAD * DIM_D / 4)

__global__ __launch_bounds__(256) void conv_kernel(
    const float* __restrict__ W1,
    const float* __restrict__ W2,
    const float* __restrict__ slots,
    const float* __restrict__ pos)
{
    int i = blockIdx.x * 256 + threadIdx.x;
    if (i < W1_F4) {
        *(uint2*)&g_W1h[i * 4] = f4_to_h4(*(const float4*)&W1[i * 4]);
    } else if (i < W1_F4 + W2_F4) {
        int j = i - W1_F4;
        *(uint2*)&g_W2h[j * 4] = f4_to_h4(*(const float4*)&W2[j * 4]);
    } else if (i < W1_F4 + W2_F4 + A_F4) {
        int j = i - W1_F4 - W2_F4;
        int m = (j * 4) / DIM_D;
        int c = (j * 4) % DIM_D;
        float4 v = make_float4(0.f, 0.f, 0.f, 0.f);
        if (m < 128)      v = *(const float4*)&slots[m * DIM_D + c];
        else if (m < MSP) v = *(const float4*)&pos[(m - 128) * DIM_D + c];
        *(uint2*)&g_Ah[j * 4] = f4_to_h4(v);
    }
}

#define LDA 72     // halves (64 + 8 pad)
#define LDB 136    // halves (128 + 8 pad)
#define ASZ (64 * LDA)          // halves per A stage
#define BSZ (64 * LDB)          // halves per B stage
#define NSTG 4
#define STG_SMEM (NSTG * (ASZ + BSZ) * 2)   // 106496 bytes

// ---------------------------------------------------------------------------
// Kernel 1: GEMM1  g_Ah(384x768) @ g_W1h(768x3072) -> g_SP1 (fp32)
// BM=64 BN=128 BK=64, 256 thr, warp 32x32, 4-stage pipeline. grid (24,6)
// ---------------------------------------------------------------------------
__global__ __launch_bounds__(256) void gemm_small_kernel()
{
    constexpr int KT = DIM_D / 64;   // 12

    extern __shared__ __align__(16) char smraw[];
    __half* As = (__half*)smraw;          // NSTG * ASZ
    __half* Bs = As + NSTG * ASZ;         // NSTG * BSZ
    const unsigned sb  = smem_u32(smraw);
    const unsigned sbB = sb + NSTG * ASZ * 2;

    const int h0  = blockIdx.x * 128;
    const int m0  = blockIdx.y * 64;
    const int tid = threadIdx.x;
    const int wid = tid >> 5;
    const int warp_m = wid >> 2;
    const int warp_n = wid & 3;

    wmma::fragment<wmma::accumulator, 16, 16, 16, float> acc[2][2];
#pragma unroll
    for (int i = 0; i < 2; i++)
#pragma unroll
        for (int j = 0; j < 2; j++)
            wmma::fill_fragment(acc[i][j], 0.0f);

    const int ar = tid >> 2, ac = (tid & 3) * 8;
    const int br = tid >> 4, bc = (tid & 15) * 8;

    const __half* gA = g_Ah + (size_t)(m0 + ar) * DIM_D + ac;

#define LOAD1(kt, st)                                                             \
    {                                                                             \
        unsigned sA0 = sb + (st) * ASZ * 2;                                       \
        cp16u(sA0 + (ar * LDA + ac) * 2,        gA + (kt) * 64);                  \
        cp16u(sA0 + (ar * LDA + ac + 32) * 2,   gA + (kt) * 64 + 32);             \
        const __half* gB = g_W1h + (size_t)((kt) * 64 + br) * DIM_H + h0 + bc;    \
        unsigned sB0 = sbB + (st) * BSZ * 2;                                      \
        cp16u(sB0 + (br * LDB + bc) * 2,        gB);                              \
        cp16u(sB0 + ((br + 16) * LDB + bc) * 2, gB + (size_t)16 * DIM_H);         \
        cp16u(sB0 + ((br + 32) * LDB + bc) * 2, gB + (size_t)32 * DIM_H);         \
        cp16u(sB0 + ((br + 48) * LDB + bc) * 2, gB + (size_t)48 * DIM_H);         \
    }

#pragma unroll
    for (int p = 0; p < NSTG - 1; p++) {
        LOAD1(p, p);
        asm volatile("cp.async.commit_group;");
    }

    for (int kt = 0; kt < KT; kt++) {
        asm volatile("cp.async.wait_group %0;" :: "n"(NSTG - 2));
        __syncthreads();
        if (kt + NSTG - 1 < KT) {
            LOAD1(kt + NSTG - 1, (kt + NSTG - 1) & (NSTG - 1));
        }
        asm volatile("cp.async.commit_group;");
        const __half* sA = As + (kt & (NSTG - 1)) * ASZ;
        const __half* sB = Bs + (kt & (NSTG - 1)) * BSZ;
#pragma unroll
        for (int ks = 0; ks < 64; ks += 16) {
            wmma::fragment<wmma::matrix_a, 16, 16, 16, __half, wmma::row_major> af[2];
            wmma::fragment<wmma::matrix_b, 16, 16, 16, __half, wmma::row_major> bf[2];
#pragma unroll
            for (int i = 0; i < 2; i++)
                wmma::load_matrix_sync(af[i], &sA[(warp_m * 32 + i * 16) * LDA + ks], LDA);
#pragma unroll
            for (int j = 0; j < 2; j++)
                wmma::load_matrix_sync(bf[j], &sB[ks * LDB + warp_n * 32 + j * 16], LDB);
#pragma unroll
            for (int i = 0; i < 2; i++)
#pragma unroll
                for (int j = 0; j < 2; j++)
                    wmma::mma_sync(acc[i][j], af[i], bf[j], acc[i][j]);
        }
    }
#undef LOAD1

#pragma unroll
    for (int i = 0; i < 2; i++)
#pragma unroll
        for (int j = 0; j < 2; j++)
            wmma::store_matrix_sync(
                &g_SP1[(size_t)(m0 + warp_m * 32 + i * 16) * DIM_H + h0 + warp_n * 32 + j * 16],
                acc[i][j], DIM_H, wmma::mem_row_major);
}

// ---------------------------------------------------------------------------
// Kernel 2: combine  Gh[b*196+n, h] = fp16( 0.125 * sum_k relu(S1[b,k,h]+P1[n,h]+b1[h]) )
// grid (14 n-chunks, 3 h-chunks, 16 b) = 672 blocks
// ---------------------------------------------------------------------------
__global__ __launch_bounds__(256) void combine_kernel(const float* __restrict__ b1)
{
    const int b  = blockIdx.z;
    const int h0 = blockIdx.y * 1024 + threadIdx.x * 4;
    const int n0 = blockIdx.x * 14;

    float4 s[8];
#pragma unroll
    for (int k = 0; k < 8; k++)
        s[k] = *(const float4*)&g_SP1[(size_t)(b * 8 + k) * DIM_H + h0];
    float4 bb = *(const float4*)&b1[h0];
#pragma unroll
    for (int k = 0; k < 8; k++) {
        s[k].x += bb.x; s[k].y += bb.y; s[k].z += bb.z; s[k].w += bb.w;
    }

#pragma unroll 2
    for (int n = 0; n < 14; n++) {
        int nn = n0 + n;
        float4 p = *(const float4*)&g_SP1[(size_t)(128 + nn) * DIM_H + h0];
        float4 a;
        a.x = a.y = a.z = a.w = 0.0f;
#pragma unroll
        for (int k = 0; k < 8; k++) {
            a.x += fmaxf(s[k].x + p.x, 0.0f);
            a.y += fmaxf(s[k].y + p.y, 0.0f);
            a.z += fmaxf(s[k].z + p.z, 0.0f);
            a.w += fmaxf(s[k].w + p.w, 0.0f);
        }
        a.x *= 0.125f; a.y *= 0.125f; a.z *= 0.125f; a.w *= 0.125f;
        *(uint2*)&g_Gh[(size_t)(b * DIM_N + nn) * DIM_H + h0] = f4_to_h4(a);
    }
}

// ---------------------------------------------------------------------------
// Pass 2 (fp16): out(3136x768) = Gh(3200x3072) @ W2h(3072x768) + b2
// BM=64 BN=128 BK=64, 256 thr, warp 32x32, 4-stage pipeline, wait_group 2.
// grid (6,50)=300 CTAs, 2 CTAs/SM (smem 104KB x2 = 208KB <= 228KB).
// ---------------------------------------------------------------------------
__global__ __launch_bounds__(256) void pass2_kernel(
    const float* __restrict__ b2,
    float* __restrict__ out)
{
    constexpr int KT  = DIM_H / 64;   // 48
    constexpr int LDC = 132;          // floats

    extern __shared__ __align__(16) char smraw[];
    __half* As = (__half*)smraw;          // NSTG * ASZ
    __half* Bs = As + NSTG * ASZ;         // NSTG * BSZ
    float*  Cs = (float*)smraw;           // epilogue reuse: 64*132*4 = 33792 B

    const unsigned sb  = smem_u32(smraw);
    const unsigned sbB = sb + NSTG * ASZ * 2;

    const int o0  = blockIdx.x * 128;
    const int m0  = blockIdx.y * 64;
    const int tid = threadIdx.x;
    const int wid = tid >> 5;
    const int warp_m = wid >> 2;
    const int warp_n = wid & 3;

    wmma::fragment<wmma::accumulator, 16, 16, 16, float> acc[2][2];
#pragma unroll
    for (int i = 0; i < 2; i++)
#pragma unroll
        for (int j = 0; j < 2; j++)
            wmma::fill_fragment(acc[i][j], 0.0f);

    const int ar = tid >> 2, ac = (tid & 3) * 8;
    const int br = tid >> 4, bc = (tid & 15) * 8;

    const __half* gA = g_Gh + (size_t)(m0 + ar) * DIM_H + ac;

#define LOAD2(kt, st)                                                             \
    {                                                                             \
        unsigned sA0 = sb + (st) * ASZ * 2;                                       \
        cp16u(sA0 + (ar * LDA + ac) * 2,        gA + (kt) * 64);                  \
        cp16u(sA0 + (ar * LDA + ac + 32) * 2,   gA + (kt) * 64 + 32);             \
        const __half* gB = g_W2h + (size_t)((kt) * 64 + br) * DIM_DOUT + o0 + bc; \
        unsigned sB0 = sbB + (st) * BSZ * 2;                                      \
        cp16u(sB0 + (br * LDB + bc) * 2,        gB);                              \
        cp16u(sB0 + ((br + 16) * LDB + bc) * 2, gB + 16 * DIM_DOUT);              \
        cp16u(sB0 + ((br + 32) * LDB + bc) * 2, gB + 32 * DIM_DOUT);              \
        cp16u(sB0 + ((br + 48) * LDB + bc) * 2, gB + 48 * DIM_DOUT);              \
    }

#pragma unroll
    for (int p = 0; p < NSTG - 1; p++) {
        LOAD2(p, p);
        asm volatile("cp.async.commit_group;");
    }

    for (int kt = 0; kt < KT; kt++) {
        asm volatile("cp.async.wait_group %0;" :: "n"(NSTG - 2));
        __syncthreads();
        if (kt + NSTG - 1 < KT) {
            LOAD2(kt + NSTG - 1, (kt + NSTG - 1) & (NSTG - 1));
        }
        asm volatile("cp.async.commit_group;");
        const __half* sA = As + (kt & (NSTG - 1)) * ASZ;
        const __half* sB = Bs + (kt & (NSTG - 1)) * BSZ;
#pragma unroll
        for (int ks = 0; ks < 64; ks += 16) {
            wmma::fragment<wmma::matrix_a, 16, 16, 16, __half, wmma::row_major> af[2];
            wmma::fragment<wmma::matrix_b, 16, 16, 16, __half, wmma::row_major> bf[2];
#pragma unroll
            for (int i = 0; i < 2; i++)
                wmma::load_matrix_sync(af[i], &sA[(warp_m * 32 + i * 16) * LDA + ks], LDA);
#pragma unroll
            for (int j = 0; j < 2; j++)
                wmma::load_matrix_sync(bf[j], &sB[ks * LDB + warp_n * 32 + j * 16], LDB);
#pragma unroll
            for (int i = 0; i < 2; i++)
#pragma unroll
                for (int j = 0; j < 2; j++)
                    wmma::mma_sync(acc[i][j], af[i], bf[j], acc[i][j]);
        }
    }
#undef LOAD2

    // drain + epilogue via smem (reuses tile space), add bias, write out
    asm volatile("cp.async.wait_group 0;");
    __syncthreads();
#pragma unroll
    for (int i = 0; i < 2; i++)
#pragma unroll
        for (int j = 0; j < 2; j++)
            wmma::store_matrix_sync(
                &Cs[(warp_m * 32 + i * 16) * LDC + warp_n * 32 + j * 16],
                acc[i][j], LDC, wmma::mem_row_major);
    __syncthreads();

#pragma unroll
    for (int p = 0; p < 8; p++) {
        int o = p * 256 + tid;
        int r = o >> 5, c4 = (o & 31) * 4;
        int m = m0 + r;
        if (m < M2) {
            float4 v = *(float4*)&Cs[r * LDC + c4];
            float4 bb = *(const float4*)&b2[o0 + c4];
            v.x += bb.x; v.y += bb.y; v.z += bb.z; v.w += bb.w;
            *(float4*)&out[(size_t)m * DIM_DOUT + o0 + c4] = v;
        }
    }
}

// ---------------------------------------------------------------------------
extern "C" void kernel_launch(void* const* d_in, const int* in_sizes, int n_in,
                              void* d_out, int out_size)
{
    const float* slots = (const float*)d_in[0];   // (16,8,768)
    const float* pos   = (const float*)d_in[1];   // (196,768)
    // d_in[2] = map_alpha : softmax over K of identical values == 1/8 exactly
    const float* W1    = (const float*)d_in[3];   // (768,3072)
    const float* b1    = (const float*)d_in[4];   // (3072,)
    const float* W2    = (const float*)d_in[5];   // (3072,768)
    const float* b2    = (const float*)d_in[6];   // (768,)
    float* out = (float*)d_out;                   // (16,196,768)

    static_assert(STG_SMEM == 106496, "smem");
    cudaFuncSetAttribute(gemm_small_kernel,
                         cudaFuncAttributeMaxDynamicSharedMemorySize, STG_SMEM);
    cudaFuncSetAttribute(pass2_kernel,
                         cudaFuncAttributeMaxDynamicSharedMemorySize, STG_SMEM);

    constexpr int CONV_BLKS = (W1_F4 + W2_F4 + A_F4 + 255) / 256;
    conv_kernel<<<CONV_BLKS, 256>>>(W1, W2, slots, pos);

    dim3 gs(DIM_H / 128, MSP_PAD / 64);             // (24, 6)
    gemm_small_kernel<<<gs, 256, STG_SMEM>>>();

    dim3 gc(14, 3, DIM_B);                          // (14,3,16) = 672 blocks
    combine_kernel<<<gc, 256>>>(b1);

    dim3 g2(DIM_DOUT / 128, M2_PAD / 64);           // (6, 50) = 300 blocks
    pass2_kernel<<<g2, 256, STG_SMEM>>>(b2, out);
}